// round 12
// baseline (speedup 1.0000x reference)
#include <cuda_runtime.h>
#include <cuda_bf16.h>
#include <cstdint>

#define BSZ   8
#define Hd    128
#define Ld    4096
#define LF    2049
#define NCOL  (BSZ*LF)      /* 16392 */
#define NCOLP 16512         /* multiple of 64 */
#define NT    64            /* cols per CTA */

// ---------------- scratch (device globals: allocation-free) ----------------
__device__ float2 g_T [128*128];              // scratch D*F (fp32)
__device__ __nv_bfloat16 g_AB[4][128*128];    // B~ planes: ArH ArL AiH AiL  [p][m] = A[row=p][k=m]
__device__ __nv_bfloat16 g_AE[4][128*256];    // [C~|D~] planes              [n][k]
__device__ __nv_bfloat16 g_Pb[4][128*NCOLP];  // Uhat split planes
__device__ float2 g_Ys[128*NCOLP];            // spectral output (fp32)

__device__ __forceinline__ float2 cmulf(float2 a, float2 b) {
    return make_float2(a.x*b.x - a.y*b.y, a.x*b.y + a.y*b.x);
}
__device__ __forceinline__ void split2(float v, __nv_bfloat16& h, __nv_bfloat16& l) {
    h = __float2bfloat16(v);
    l = __float2bfloat16(v - __bfloat162float(h));
}

// ---------------- folds (write bf16 planes directly) ----------------
__global__ void k_fold1(const float* __restrict__ C2, const float* __restrict__ Bb2,
                        const float* __restrict__ Dm) {
    __shared__ float2 twH[128];
    int bx = blockIdx.x, t = threadIdx.x;
    { float s,c; sincospif(-(float)t/64.0f, &s, &c); twH[t] = make_float2(c,s); }
    __syncthreads();
    __nv_bfloat16 h, l;
    if (bx < 128) {
        int p = bx, m = t;
        float2 acc = make_float2(0.f,0.f);
        for (int q = 0; q < 128; q++) {
            float2 w = twH[(q*m)&127];
            float br = Bb2[(p*128+q)*2], bi = Bb2[(p*128+q)*2+1];
            acc.x += br*w.x - bi*w.y;
            acc.y += br*w.y + bi*w.x;
        }
        int idx = p*128 + m;            // A layout [row=p][k=m]
        split2(acc.x,h,l); g_AB[0][idx]=h; g_AB[1][idx]=l;
        split2(acc.y,h,l); g_AB[2][idx]=h; g_AB[3][idx]=l;
    } else if (bx < 256) {
        int n = bx-128, p = t;
        float2 acc = make_float2(0.f,0.f);
        for (int hh = 0; hh < 128; hh++) {
            float2 w = twH[(n*hh)&127]; w.y = -w.y;
            float cr = C2[(hh*128+p)*2], ci = C2[(hh*128+p)*2+1];
            acc.x += cr*w.x - ci*w.y;
            acc.y += cr*w.y + ci*w.x;
        }
        acc.x *= (1.0f/128.0f); acc.y *= (1.0f/128.0f);
        int idx = n*256 + p;            // [row=n][k=p]
        split2(acc.x,h,l); g_AE[0][idx]=h; g_AE[1][idx]=l;
        split2(acc.y,h,l); g_AE[2][idx]=h; g_AE[3][idx]=l;
    } else {
        int hh = bx-256, m = t;
        float2 acc = make_float2(0.f,0.f);
        for (int q = 0; q < 128; q++) {
            float2 w = twH[(q*m)&127];
            float d = Dm[hh*128+q];
            acc.x += d*w.x; acc.y += d*w.y;
        }
        g_T[hh*128+m] = acc;
    }
}

__global__ void k_fold2() {
    __shared__ float2 twH[128];
    int n = blockIdx.x, m = threadIdx.x;
    { float s,c; sincospif(-(float)m/64.0f, &s, &c); twH[m] = make_float2(c,s); }
    __syncthreads();
    float2 acc = make_float2(0.f,0.f);
    for (int hh = 0; hh < 128; hh++) {
        float2 w = twH[(n*hh)&127]; w.y = -w.y;
        float2 tv = g_T[hh*128+m];
        acc.x += tv.x*w.x - tv.y*w.y;
        acc.y += tv.x*w.y + tv.y*w.x;
    }
    acc.x *= (1.0f/128.0f); acc.y *= (1.0f/128.0f);
    int idx = n*256 + 128 + m;          // [row=n][k=128+m]
    __nv_bfloat16 h, l;
    split2(acc.x,h,l); g_AE[0][idx]=h; g_AE[1][idx]=l;
    split2(acc.y,h,l); g_AE[2][idx]=h; g_AE[3][idx]=l;
}

// ---------------- Stockham radix-4, N=4096 = 4^6 ----------------------------
__device__ __forceinline__ void stockham4(float2* sa, float2* sb, const float2* tw, bool inv) {
    float2* src = sa; float2* dst = sb;
    #pragma unroll 1
    for (int s = 0; s < 6; s++) {
        int t2 = 2*s;
        int nq = 1024 >> t2;
        int mask = (1<<t2) - 1;
        for (int idx = threadIdx.x; idx < 1024; idx += blockDim.x) {
            int p = idx >> t2;
            int q = idx & mask;
            float2 a0 = src[q + ( p         << t2)];
            float2 a1 = src[q + ((p +   nq) << t2)];
            float2 a2 = src[q + ((p + 2*nq) << t2)];
            float2 a3 = src[q + ((p + 3*nq) << t2)];
            float2 s02 = make_float2(a0.x+a2.x, a0.y+a2.y);
            float2 d02 = make_float2(a0.x-a2.x, a0.y-a2.y);
            float2 s13 = make_float2(a1.x+a3.x, a1.y+a3.y);
            float2 d13 = make_float2(a1.x-a3.x, a1.y-a3.y);
            float2 jd = inv ? make_float2(-d13.y, d13.x) : make_float2(d13.y, -d13.x);
            float2 b0 = make_float2(s02.x+s13.x, s02.y+s13.y);
            float2 b1 = make_float2(d02.x+jd.x,  d02.y+jd.y);
            float2 b2 = make_float2(s02.x-s13.x, s02.y-s13.y);
            float2 b3 = make_float2(d02.x-jd.x,  d02.y-jd.y);
            int k = p << t2;
            float2 w1 = tw[k], w2 = tw[2*k], w3 = tw[3*k];
            if (inv) { w1.y=-w1.y; w2.y=-w2.y; w3.y=-w3.y; }
            dst[q + ((4*p  ) << t2)] = b0;
            dst[q + ((4*p+1) << t2)] = cmulf(b1, w1);
            dst[q + ((4*p+2) << t2)] = cmulf(b2, w2);
            dst[q + ((4*p+3) << t2)] = cmulf(b3, w3);
        }
        __syncthreads();
        float2* tmp = src; src = dst; dst = tmp;
    }
}

#define FFT_SMEM ((4096+4096+3072) * (int)sizeof(float2))   /* 90112 B */

__global__ void __launch_bounds__(512) k_fft_fwd(const float* __restrict__ u) {
    extern __shared__ float2 sm[];
    float2* sa = sm; float2* sb = sm+4096; float2* tw = sm+8192;
    int r0 = blockIdx.x*2;
    int b = r0 >> 7, h0 = r0 & 127;
    const float* u0 = u + (size_t)r0*Ld;
    for (int t = threadIdx.x; t < Ld; t += blockDim.x)
        sa[t] = make_float2(u0[t], u0[t+Ld]);
    for (int k = threadIdx.x; k < 3072; k += blockDim.x) {
        float s,c; sincospif(-(float)k/2048.0f,&s,&c); tw[k]=make_float2(c,s);
    }
    __syncthreads();
    stockham4(sa, sb, tw, false);
    size_t o1 = (size_t)h0*NCOLP + b*LF;
    size_t o2 = o1 + NCOLP;
    for (int k = threadIdx.x; k < LF; k += blockDim.x) {
        float2 zk = sa[k];
        float2 zn = sa[(4096-k)&4095];
        float2 x1 = make_float2(0.5f*(zk.x+zn.x), 0.5f*(zk.y-zn.y));
        float2 x2 = make_float2(0.5f*(zk.y+zn.y), 0.5f*(zn.x-zk.x));
        __nv_bfloat16 h, l;
        split2(x1.x,h,l); g_Pb[0][o1+k]=h; g_Pb[1][o1+k]=l;
        split2(x1.y,h,l); g_Pb[2][o1+k]=h; g_Pb[3][o1+k]=l;
        split2(x2.x,h,l); g_Pb[0][o2+k]=h; g_Pb[1][o2+k]=l;
        split2(x2.y,h,l); g_Pb[2][o2+k]=h; g_Pb[3][o2+k]=l;
    }
}

// ---------------- fused tensor-core pipeline --------------------------------
// K-chunk = 32 (12 chunks: 4 GEMM1, 8 GEMM2) -> 24 barriers.
#define USTR 72
#define UPL  (128*USTR)
#define AKSTR 40
#define APL2 (128*AKSTR)                      /* 5120 bf16 per A plane per buffer */
#define FUSED_SMEM ((8*UPL + 2*4*APL2) * 2)   /* 229376 bytes */

__device__ __forceinline__ uint32_t cvta_s(const void* p) {
    return (uint32_t)__cvta_generic_to_shared(p);
}
__device__ __forceinline__ void cp16(uint32_t s, const void* g) {
    asm volatile("cp.async.cg.shared.global [%0], [%1], 16;" :: "r"(s), "l"(g));
}
__device__ __forceinline__ void cp_commit() { asm volatile("cp.async.commit_group;"); }
__device__ __forceinline__ void cp_wait1()  { asm volatile("cp.async.wait_group 1;"); }
__device__ __forceinline__ void ldsm_x4(uint32_t& r0, uint32_t& r1, uint32_t& r2, uint32_t& r3,
                                        uint32_t addr) {
    asm volatile("ldmatrix.sync.aligned.m8n8.x4.shared.b16 {%0,%1,%2,%3}, [%4];"
                 : "=r"(r0), "=r"(r1), "=r"(r2), "=r"(r3) : "r"(addr));
}
__device__ __forceinline__ void ldsm_x4t(uint32_t& r0, uint32_t& r1, uint32_t& r2, uint32_t& r3,
                                         uint32_t addr) {
    asm volatile("ldmatrix.sync.aligned.m8n8.x4.trans.shared.b16 {%0,%1,%2,%3}, [%4];"
                 : "=r"(r0), "=r"(r1), "=r"(r2), "=r"(r3) : "r"(addr));
}
__device__ __forceinline__ void mma_bf16(float* c, const uint32_t* a, const uint32_t* b) {
    asm volatile("mma.sync.aligned.m16n8k16.row.col.f32.bf16.bf16.f32 "
                 "{%0,%1,%2,%3}, {%4,%5,%6,%7}, {%8,%9}, {%0,%1,%2,%3};"
                 : "+f"(c[0]), "+f"(c[1]), "+f"(c[2]), "+f"(c[3])
                 : "r"(a[0]), "r"(a[1]), "r"(a[2]), "r"(a[3]), "r"(b[0]), "r"(b[1]));
}

// 256 threads: 8 warps = 4(M) x 2(N); warp tile 32(M) x 32(N).
// Accumulators: P = Ar*Br, Q = Ai*Bi, I = Ar*Bi + Ai*Br;  real = P - Q.
__global__ void __launch_bounds__(256, 1) k_fused(const float* __restrict__ Lam) {
    extern __shared__ __nv_bfloat16 smem[];
    __nv_bfloat16* Ub = smem;                 // 4 planes
    __nv_bfloat16* Wb = smem + 4*UPL;         // 4 planes
    __nv_bfloat16* Ab = smem + 8*UPL;         // 2 bufs x 4 planes

    const int tid  = threadIdx.x;
    const int warp = tid >> 5, lane = tid & 31;
    const int wm = warp & 3, wn = warp >> 2;      // 4 warps down M, 2 across N
    const int col0 = blockIdx.x*NT;
    const int l16 = lane & 15, lhi = (lane >> 4) << 3;

    float accP[2][4][4], accQ[2][4][4], accI[2][4][4];
    #pragma unroll
    for (int mf=0;mf<2;mf++)
        #pragma unroll
        for (int nf=0;nf<4;nf++)
            #pragma unroll
            for (int r=0;r<4;r++) { accP[mf][nf][r]=0.f; accQ[mf][nf][r]=0.f; accI[mf][nf][r]=0.f; }

    auto stageU = [&]() {
        #pragma unroll
        for (int i = 0; i < 16; i++) {
            int idx = tid + i*256;
            int pl = idx >> 10, rem = idx & 1023;
            int row = rem >> 3, c = rem & 7;
            cp16(cvta_s(Ub + pl*UPL + row*USTR + c*8),
                 g_Pb[pl] + (size_t)row*NCOLP + col0 + c*8);
        }
    };
    // stage one K=32 A chunk (cc in 0..11; 0..3 = Bt, 4..11 = E)
    auto stageA = [&](int cc) {
        const __nv_bfloat16* Asrc;
        int ks, aplg, k0;
        if (cc < 4) { Asrc = g_AB[0]; ks = 128; aplg = 128*128; k0 = cc*32; }
        else        { Asrc = g_AE[0]; ks = 256; aplg = 128*256; k0 = (cc-4)*32; }
        __nv_bfloat16* dst = Ab + (cc&1)*(4*APL2);
        #pragma unroll
        for (int i = 0; i < 8; i++) {
            int idx = tid + i*256;
            int pl = idx >> 9, rem = idx & 511;
            int row = rem >> 2, c = rem & 3;
            cp16(cvta_s(dst + pl*APL2 + row*AKSTR + c*8),
                 Asrc + (size_t)pl*aplg + (size_t)row*ks + k0 + c*8);
        }
    };

    stageU(); stageA(0); cp_commit();

    #pragma unroll 1
    for (int c = 0; c < 12; c++) {
        if (c+1 < 12) stageA(c+1);     // buf (c+1)&1, protected by iter c-1's trailing barrier
        cp_commit();

        if (c == 4) {
            // ---- GEMM1 epilogue: real = P-Q, Cauchy, split W into smem, reset acc
            #pragma unroll
            for (int mf = 0; mf < 2; mf++) {
                #pragma unroll
                for (int h = 0; h < 2; h++) {
                    int row = wm*32 + mf*16 + (lane>>2) + h*8;
                    float lre = Lam[2*row], lim = Lam[2*row+1];
                    #pragma unroll
                    for (int nf = 0; nf < 4; nf++) {
                        int col = wn*32 + nf*8 + (lane&3)*2;
                        float vr0 = accP[mf][nf][h*2+0] - accQ[mf][nf][h*2+0];
                        float vi0 = accI[mf][nf][h*2+0];
                        float vr1 = accP[mf][nf][h*2+1] - accQ[mf][nf][h*2+1];
                        float vi1 = accI[mf][nf][h*2+1];
                        int gc = col0 + col;
                        int l0 = gc % 2049, l1 = (gc+1) % 2049;
                        float om0 = 1.5339807878856412e-3f * (float)l0;
                        float om1 = 1.5339807878856412e-3f * (float)l1;
                        float dre = -lre;
                        float di0 = om0 - lim, di1 = om1 - lim;
                        float iv0 = 1.0f/(dre*dre + di0*di0);
                        float iv1 = 1.0f/(dre*dre + di1*di1);
                        float kr0 = dre*iv0, ki0 = -di0*iv0;
                        float kr1 = dre*iv1, ki1 = -di1*iv1;
                        float tr0 = vr0*kr0 - vi0*ki0, ti0 = vr0*ki0 + vi0*kr0;
                        float tr1 = vr1*kr1 - vi1*ki1, ti1 = vr1*ki1 + vi1*kr1;
                        int off = row*USTR + col;
                        __nv_bfloat16 h0,l0b,h1,l1b;
                        split2(tr0,h0,l0b); split2(tr1,h1,l1b);
                        *reinterpret_cast<__nv_bfloat162*>(&Wb[0*UPL+off]) = __nv_bfloat162(h0,h1);
                        *reinterpret_cast<__nv_bfloat162*>(&Wb[1*UPL+off]) = __nv_bfloat162(l0b,l1b);
                        split2(ti0,h0,l0b); split2(ti1,h1,l1b);
                        *reinterpret_cast<__nv_bfloat162*>(&Wb[2*UPL+off]) = __nv_bfloat162(h0,h1);
                        *reinterpret_cast<__nv_bfloat162*>(&Wb[3*UPL+off]) = __nv_bfloat162(l0b,l1b);
                        #pragma unroll
                        for (int r=0;r<2;r++) {
                            accP[mf][nf][h*2+r]=0.f; accQ[mf][nf][h*2+r]=0.f; accI[mf][nf][h*2+r]=0.f;
                        }
                    }
                }
            }
        }
        cp_wait1();
        __syncthreads();   // chunk c data ready; Wb visible at c==4

        const __nv_bfloat16* Bbase; int krow;
        if (c < 4)       { Bbase = Ub; krow = c*32; }
        else if (c < 8)  { Bbase = Wb; krow = (c-4)*32; }
        else             { Bbase = Ub; krow = (c-8)*32; }
        const __nv_bfloat16* As = Ab + (c&1)*(4*APL2);

        // ---- preload BOTH kk halves of B fragments (16 independent ldsm)
        uint32_t b[2][4][4][2];
        #pragma unroll
        for (int half = 0; half < 2; half++)
            #pragma unroll
            for (int q = 0; q < 4; q++)
                #pragma unroll
                for (int np = 0; np < 2; np++) {
                    uint32_t addr = cvta_s(Bbase + q*UPL + (krow + half*16 + l16)*USTR
                                           + wn*32 + np*16 + lhi);
                    ldsm_x4t(b[half][q][2*np][0], b[half][q][2*np][1],
                             b[half][q][2*np+1][0], b[half][q][2*np+1][1], addr);
                }
        #pragma unroll
        for (int half = 0; half < 2; half++) {
            const int kk = half*16;
            #pragma unroll
            for (int p = 0; p < 4; p++) {
                uint32_t a[2][4];
                #pragma unroll
                for (int mf = 0; mf < 2; mf++) {
                    uint32_t addr = cvta_s(As + p*APL2 + (wm*32 + mf*16 + l16)*AKSTR + kk + lhi);
                    ldsm_x4(a[mf][0], a[mf][1], a[mf][2], a[mf][3], addr);
                }
                #pragma unroll
                for (int mf = 0; mf < 2; mf++)
                    #pragma unroll
                    for (int nf = 0; nf < 4; nf++) {
                        if (p == 0) {                       // ArH
                            mma_bf16(accP[mf][nf], a[mf], b[half][0][nf]);
                            mma_bf16(accP[mf][nf], a[mf], b[half][1][nf]);
                            mma_bf16(accI[mf][nf], a[mf], b[half][2][nf]);
                            mma_bf16(accI[mf][nf], a[mf], b[half][3][nf]);
                        } else if (p == 1) {                // ArL
                            mma_bf16(accP[mf][nf], a[mf], b[half][0][nf]);
                            mma_bf16(accI[mf][nf], a[mf], b[half][2][nf]);
                        } else if (p == 2) {                // AiH
                            mma_bf16(accQ[mf][nf], a[mf], b[half][2][nf]);
                            mma_bf16(accQ[mf][nf], a[mf], b[half][3][nf]);
                            mma_bf16(accI[mf][nf], a[mf], b[half][0][nf]);
                            mma_bf16(accI[mf][nf], a[mf], b[half][1][nf]);
                        } else {                            // AiL
                            mma_bf16(accQ[mf][nf], a[mf], b[half][2][nf]);
                            mma_bf16(accI[mf][nf], a[mf], b[half][0][nf]);
                        }
                    }
            }
        }
        __syncthreads();   // all warps done reading buf c&1 before restage
    }

    // ---- GEMM2 epilogue: real = P-Q, write Ys (fp32)
    #pragma unroll
    for (int mf = 0; mf < 2; mf++) {
        #pragma unroll
        for (int h = 0; h < 2; h++) {
            int row = wm*32 + mf*16 + (lane>>2) + h*8;
            #pragma unroll
            for (int nf = 0; nf < 4; nf++) {
                int col = col0 + wn*32 + nf*8 + (lane&3)*2;
                float4 o = make_float4(accP[mf][nf][h*2+0] - accQ[mf][nf][h*2+0],
                                       accI[mf][nf][h*2+0],
                                       accP[mf][nf][h*2+1] - accQ[mf][nf][h*2+1],
                                       accI[mf][nf][h*2+1]);
                *reinterpret_cast<float4*>(&g_Ys[(size_t)row*NCOLP + col]) = o;
            }
        }
    }
}

// ---------------- inverse FFT + GELU ----------------------------------------
__global__ void __launch_bounds__(512) k_fft_inv(float* __restrict__ out) {
    extern __shared__ float2 sm[];
    float2* sa = sm; float2* sb = sm+4096; float2* tw = sm+8192;
    int r0 = blockIdx.x*2;
    int b = r0 >> 7, h0 = r0 & 127;
    const float2* in0 = g_Ys + (size_t)h0*NCOLP + b*LF;
    for (int k = threadIdx.x; k < LF; k += blockDim.x) {
        float2 y1 = in0[k];
        float2 y2 = in0[NCOLP+k];
        if (k == 0 || k == 2048) { y1.y = 0.f; y2.y = 0.f; }
        sa[k] = make_float2(y1.x - y2.y, y1.y + y2.x);
        if (k > 0 && k < 2048)
            sa[4096-k] = make_float2(y1.x + y2.y, y2.x - y1.y);
    }
    for (int k = threadIdx.x; k < 3072; k += blockDim.x) {
        float s,c; sincospif(-(float)k/2048.0f,&s,&c); tw[k]=make_float2(c,s);
    }
    __syncthreads();
    stockham4(sa, sb, tw, true);
    float* o0 = out + (size_t)r0*Ld;
    const float sc = 1.0f/4096.0f;
    for (int t = threadIdx.x; t < Ld; t += blockDim.x) {
        float v0 = sa[t].x*sc, v1 = sa[t].y*sc;
        o0[t]    = 0.5f*v0*(1.0f + erff(v0*0.70710678118654752f));
        o0[t+Ld] = 0.5f*v1*(1.0f + erff(v1*0.70710678118654752f));
    }
}

// ---------------- launch ----------------------------------------------------
extern "C" void kernel_launch(void* const* d_in, const int* in_sizes, int n_in,
                              void* d_out, int out_size) {
    (void)in_sizes; (void)n_in; (void)out_size;
    const float* u   = (const float*)d_in[0];
    const float* C2  = (const float*)d_in[1];
    const float* Bb2 = (const float*)d_in[2];
    const float* Dm  = (const float*)d_in[3];
    const float* Lam = (const float*)d_in[4];
    float* out = (float*)d_out;

    cudaFuncSetAttribute(k_fft_fwd, cudaFuncAttributeMaxDynamicSharedMemorySize, FFT_SMEM);
    cudaFuncSetAttribute(k_fft_inv, cudaFuncAttributeMaxDynamicSharedMemorySize, FFT_SMEM);
    cudaFuncSetAttribute(k_fused,  cudaFuncAttributeMaxDynamicSharedMemorySize, FUSED_SMEM);

    k_fold1<<<384, 128>>>(C2, Bb2, Dm);
    k_fold2<<<128, 128>>>();
    k_fft_fwd<<<512, 512, FFT_SMEM>>>(u);
    k_fused<<<NCOLP/NT, 256, FUSED_SMEM>>>(Lam);
    k_fft_inv<<<512, 512, FFT_SMEM>>>(out);
}

// round 13
// speedup vs baseline: 1.0154x; 1.0154x over previous
#include <cuda_runtime.h>
#include <cuda_bf16.h>
#include <cstdint>

#define BSZ   8
#define Hd    128
#define Ld    4096
#define LF    2049
#define NCOL  (BSZ*LF)      /* 16392 */
#define NCOLP 16512         /* multiple of 64 */
#define NT    64            /* cols per CTA */

// ---------------- scratch (device globals: allocation-free) ----------------
__device__ float2 g_T [128*128];              // scratch D*F (fp32)
__device__ __nv_bfloat16 g_AB[4][128*128];    // B~ planes: ArH ArL AiH AiL  [p][m] = A[row=p][k=m]
__device__ __nv_bfloat16 g_AE[4][128*256];    // [C~|D~] planes              [n][k]
__device__ __nv_bfloat16 g_Pb[4][128*NCOLP];  // Uhat split planes
__device__ float2 g_Ys[128*NCOLP];            // spectral output (fp32)

__device__ __forceinline__ float2 cmulf(float2 a, float2 b) {
    return make_float2(a.x*b.x - a.y*b.y, a.x*b.y + a.y*b.x);
}
__device__ __forceinline__ void split2(float v, __nv_bfloat16& h, __nv_bfloat16& l) {
    h = __float2bfloat16(v);
    l = __float2bfloat16(v - __bfloat162float(h));
}

// ---------------- folds (write bf16 planes directly) ----------------
__global__ void k_fold1(const float* __restrict__ C2, const float* __restrict__ Bb2,
                        const float* __restrict__ Dm) {
    __shared__ float2 twH[128];
    int bx = blockIdx.x, t = threadIdx.x;
    { float s,c; sincospif(-(float)t/64.0f, &s, &c); twH[t] = make_float2(c,s); }
    __syncthreads();
    __nv_bfloat16 h, l;
    if (bx < 128) {
        int p = bx, m = t;
        float2 acc = make_float2(0.f,0.f);
        for (int q = 0; q < 128; q++) {
            float2 w = twH[(q*m)&127];
            float br = Bb2[(p*128+q)*2], bi = Bb2[(p*128+q)*2+1];
            acc.x += br*w.x - bi*w.y;
            acc.y += br*w.y + bi*w.x;
        }
        int idx = p*128 + m;            // A layout [row=p][k=m]
        split2(acc.x,h,l); g_AB[0][idx]=h; g_AB[1][idx]=l;
        split2(acc.y,h,l); g_AB[2][idx]=h; g_AB[3][idx]=l;
    } else if (bx < 256) {
        int n = bx-128, p = t;
        float2 acc = make_float2(0.f,0.f);
        for (int hh = 0; hh < 128; hh++) {
            float2 w = twH[(n*hh)&127]; w.y = -w.y;
            float cr = C2[(hh*128+p)*2], ci = C2[(hh*128+p)*2+1];
            acc.x += cr*w.x - ci*w.y;
            acc.y += cr*w.y + ci*w.x;
        }
        acc.x *= (1.0f/128.0f); acc.y *= (1.0f/128.0f);
        int idx = n*256 + p;            // [row=n][k=p]
        split2(acc.x,h,l); g_AE[0][idx]=h; g_AE[1][idx]=l;
        split2(acc.y,h,l); g_AE[2][idx]=h; g_AE[3][idx]=l;
    } else {
        int hh = bx-256, m = t;
        float2 acc = make_float2(0.f,0.f);
        for (int q = 0; q < 128; q++) {
            float2 w = twH[(q*m)&127];
            float d = Dm[hh*128+q];
            acc.x += d*w.x; acc.y += d*w.y;
        }
        g_T[hh*128+m] = acc;
    }
}

__global__ void k_fold2() {
    __shared__ float2 twH[128];
    int n = blockIdx.x, m = threadIdx.x;
    { float s,c; sincospif(-(float)m/64.0f, &s, &c); twH[m] = make_float2(c,s); }
    __syncthreads();
    float2 acc = make_float2(0.f,0.f);
    for (int hh = 0; hh < 128; hh++) {
        float2 w = twH[(n*hh)&127]; w.y = -w.y;
        float2 tv = g_T[hh*128+m];
        acc.x += tv.x*w.x - tv.y*w.y;
        acc.y += tv.x*w.y + tv.y*w.x;
    }
    acc.x *= (1.0f/128.0f); acc.y *= (1.0f/128.0f);
    int idx = n*256 + 128 + m;          // [row=n][k=128+m]
    __nv_bfloat16 h, l;
    split2(acc.x,h,l); g_AE[0][idx]=h; g_AE[1][idx]=l;
    split2(acc.y,h,l); g_AE[2][idx]=h; g_AE[3][idx]=l;
}

// ---------------- Stockham radix-8, N=4096 = 8^4 ----------------------------
// 4-point DFT core (verified radix-4 math). a[] in natural order.
__device__ __forceinline__ void r4core(const float2* a, float2* o, bool inv) {
    float2 s02 = make_float2(a[0].x+a[2].x, a[0].y+a[2].y);
    float2 d02 = make_float2(a[0].x-a[2].x, a[0].y-a[2].y);
    float2 s13 = make_float2(a[1].x+a[3].x, a[1].y+a[3].y);
    float2 d13 = make_float2(a[1].x-a[3].x, a[1].y-a[3].y);
    float2 jd = inv ? make_float2(-d13.y, d13.x) : make_float2(d13.y, -d13.x);
    o[0] = make_float2(s02.x+s13.x, s02.y+s13.y);
    o[1] = make_float2(d02.x+jd.x,  d02.y+jd.y);
    o[2] = make_float2(s02.x-s13.x, s02.y-s13.y);
    o[3] = make_float2(d02.x-jd.x,  d02.y-jd.y);
}

// Radix-8 stage: DFT8 via two DFT4 (evens/odds) + w8 rotations.
// Requires blockDim.x == 512 (one butterfly per thread per stage).
__device__ __forceinline__ void stockham8(float2* sa, float2* sb, const float2* tw, bool inv) {
    const float S = 0.70710678118654752f;
    float2* src = sa; float2* dst = sb;
    #pragma unroll 1
    for (int s = 0; s < 4; s++) {
        int t3 = 3*s;
        int mask = (1<<t3) - 1;
        int idx = threadIdx.x;
        int p = idx >> t3, q = idx & mask;
        int bp = p << t3;
        float2 a[8];
        #pragma unroll
        for (int m = 0; m < 8; m++) a[m] = src[q + bp + m*512];
        float2 ev[4] = {a[0],a[2],a[4],a[6]};
        float2 od[4] = {a[1],a[3],a[5],a[7]};
        float2 E[4], O[4];
        r4core(ev, E, inv);
        r4core(od, O, inv);
        // O[j] *= w8^j  (w8 = e^{-i pi/4} fwd, conj for inverse)
        float2 w81 = inv ? make_float2(S,  S) : make_float2(S, -S);
        float2 w83 = inv ? make_float2(-S, S) : make_float2(-S,-S);
        O[1] = cmulf(O[1], w81);
        O[2] = inv ? make_float2(-O[2].y, O[2].x) : make_float2(O[2].y, -O[2].x);
        O[3] = cmulf(O[3], w83);
        float2 A[8];
        #pragma unroll
        for (int j = 0; j < 4; j++) {
            A[j]   = make_float2(E[j].x+O[j].x, E[j].y+O[j].y);
            A[j+4] = make_float2(E[j].x-O[j].x, E[j].y-O[j].y);
        }
        int dbase = q + 8*bp;
        dst[dbase] = A[0];
        #pragma unroll
        for (int j = 1; j < 8; j++) {
            float2 w = tw[j*bp];
            if (inv) w.y = -w.y;
            dst[dbase + (j<<t3)] = cmulf(A[j], w);
        }
        __syncthreads();
        float2* t = src; src = dst; dst = t;
    }
}

#define TWN 3584
#define FFT_SMEM ((4096+4096+TWN) * (int)sizeof(float2))   /* 94208 B */

__global__ void __launch_bounds__(512) k_fft_fwd(const float* __restrict__ u) {
    extern __shared__ float2 sm[];
    float2* sa = sm; float2* sb = sm+4096; float2* tw = sm+8192;
    int r0 = blockIdx.x*2;
    int b = r0 >> 7, h0 = r0 & 127;
    const float* u0 = u + (size_t)r0*Ld;
    for (int t = threadIdx.x; t < Ld; t += blockDim.x)
        sa[t] = make_float2(u0[t], u0[t+Ld]);
    for (int k = threadIdx.x; k < TWN; k += blockDim.x) {
        float s,c; sincospif(-(float)k/2048.0f,&s,&c); tw[k]=make_float2(c,s);
    }
    __syncthreads();
    stockham8(sa, sb, tw, false);
    size_t o1 = (size_t)h0*NCOLP + b*LF;
    size_t o2 = o1 + NCOLP;
    for (int k = threadIdx.x; k < LF; k += blockDim.x) {
        float2 zk = sa[k];
        float2 zn = sa[(4096-k)&4095];
        float2 x1 = make_float2(0.5f*(zk.x+zn.x), 0.5f*(zk.y-zn.y));
        float2 x2 = make_float2(0.5f*(zk.y+zn.y), 0.5f*(zn.x-zk.x));
        __nv_bfloat16 h, l;
        split2(x1.x,h,l); g_Pb[0][o1+k]=h; g_Pb[1][o1+k]=l;
        split2(x1.y,h,l); g_Pb[2][o1+k]=h; g_Pb[3][o1+k]=l;
        split2(x2.x,h,l); g_Pb[0][o2+k]=h; g_Pb[1][o2+k]=l;
        split2(x2.y,h,l); g_Pb[2][o2+k]=h; g_Pb[3][o2+k]=l;
    }
}

// ---------------- fused tensor-core pipeline --------------------------------
// K-chunk = 32 (12 chunks: 4 GEMM1, 8 GEMM2) -> 24 barriers.
#define USTR 72
#define UPL  (128*USTR)
#define AKSTR 40
#define APL2 (128*AKSTR)                      /* 5120 bf16 per A plane per buffer */
#define FUSED_SMEM ((8*UPL + 2*4*APL2) * 2)   /* 229376 bytes */

__device__ __forceinline__ uint32_t cvta_s(const void* p) {
    return (uint32_t)__cvta_generic_to_shared(p);
}
__device__ __forceinline__ void cp16(uint32_t s, const void* g) {
    asm volatile("cp.async.cg.shared.global [%0], [%1], 16;" :: "r"(s), "l"(g));
}
__device__ __forceinline__ void cp_commit() { asm volatile("cp.async.commit_group;"); }
__device__ __forceinline__ void cp_wait1()  { asm volatile("cp.async.wait_group 1;"); }
__device__ __forceinline__ void ldsm_x4(uint32_t& r0, uint32_t& r1, uint32_t& r2, uint32_t& r3,
                                        uint32_t addr) {
    asm volatile("ldmatrix.sync.aligned.m8n8.x4.shared.b16 {%0,%1,%2,%3}, [%4];"
                 : "=r"(r0), "=r"(r1), "=r"(r2), "=r"(r3) : "r"(addr));
}
__device__ __forceinline__ void ldsm_x4t(uint32_t& r0, uint32_t& r1, uint32_t& r2, uint32_t& r3,
                                         uint32_t addr) {
    asm volatile("ldmatrix.sync.aligned.m8n8.x4.trans.shared.b16 {%0,%1,%2,%3}, [%4];"
                 : "=r"(r0), "=r"(r1), "=r"(r2), "=r"(r3) : "r"(addr));
}
__device__ __forceinline__ void mma_bf16(float* c, const uint32_t* a, const uint32_t* b) {
    asm volatile("mma.sync.aligned.m16n8k16.row.col.f32.bf16.bf16.f32 "
                 "{%0,%1,%2,%3}, {%4,%5,%6,%7}, {%8,%9}, {%0,%1,%2,%3};"
                 : "+f"(c[0]), "+f"(c[1]), "+f"(c[2]), "+f"(c[3])
                 : "r"(a[0]), "r"(a[1]), "r"(a[2]), "r"(a[3]), "r"(b[0]), "r"(b[1]));
}

// 256 threads: 8 warps = 4(M) x 2(N); warp tile 32(M) x 32(N).
// Accumulators: P = Ar*Br, Q = Ai*Bi, I = Ar*Bi + Ai*Br;  real = P - Q.
__global__ void __launch_bounds__(256, 1) k_fused(const float* __restrict__ Lam) {
    extern __shared__ __nv_bfloat16 smem[];
    __nv_bfloat16* Ub = smem;                 // 4 planes
    __nv_bfloat16* Wb = smem + 4*UPL;         // 4 planes
    __nv_bfloat16* Ab = smem + 8*UPL;         // 2 bufs x 4 planes

    const int tid  = threadIdx.x;
    const int warp = tid >> 5, lane = tid & 31;
    const int wm = warp & 3, wn = warp >> 2;      // 4 warps down M, 2 across N
    const int col0 = blockIdx.x*NT;
    const int l16 = lane & 15, lhi = (lane >> 4) << 3;

    float accP[2][4][4], accQ[2][4][4], accI[2][4][4];
    #pragma unroll
    for (int mf=0;mf<2;mf++)
        #pragma unroll
        for (int nf=0;nf<4;nf++)
            #pragma unroll
            for (int r=0;r<4;r++) { accP[mf][nf][r]=0.f; accQ[mf][nf][r]=0.f; accI[mf][nf][r]=0.f; }

    auto stageU = [&]() {
        #pragma unroll
        for (int i = 0; i < 16; i++) {
            int idx = tid + i*256;
            int pl = idx >> 10, rem = idx & 1023;
            int row = rem >> 3, c = rem & 7;
            cp16(cvta_s(Ub + pl*UPL + row*USTR + c*8),
                 g_Pb[pl] + (size_t)row*NCOLP + col0 + c*8);
        }
    };
    // stage one K=32 A chunk (cc in 0..11; 0..3 = Bt, 4..11 = E)
    auto stageA = [&](int cc) {
        const __nv_bfloat16* Asrc;
        int ks, aplg, k0;
        if (cc < 4) { Asrc = g_AB[0]; ks = 128; aplg = 128*128; k0 = cc*32; }
        else        { Asrc = g_AE[0]; ks = 256; aplg = 128*256; k0 = (cc-4)*32; }
        __nv_bfloat16* dst = Ab + (cc&1)*(4*APL2);
        #pragma unroll
        for (int i = 0; i < 8; i++) {
            int idx = tid + i*256;
            int pl = idx >> 9, rem = idx & 511;
            int row = rem >> 2, c = rem & 3;
            cp16(cvta_s(dst + pl*APL2 + row*AKSTR + c*8),
                 Asrc + (size_t)pl*aplg + (size_t)row*ks + k0 + c*8);
        }
    };

    stageU(); stageA(0); cp_commit();

    #pragma unroll 1
    for (int c = 0; c < 12; c++) {
        if (c+1 < 12) stageA(c+1);     // buf (c+1)&1, protected by iter c-1's trailing barrier
        cp_commit();

        if (c == 4) {
            // ---- GEMM1 epilogue: real = P-Q, Cauchy, split W into smem, reset acc
            #pragma unroll
            for (int mf = 0; mf < 2; mf++) {
                #pragma unroll
                for (int h = 0; h < 2; h++) {
                    int row = wm*32 + mf*16 + (lane>>2) + h*8;
                    float lre = Lam[2*row], lim = Lam[2*row+1];
                    #pragma unroll
                    for (int nf = 0; nf < 4; nf++) {
                        int col = wn*32 + nf*8 + (lane&3)*2;
                        float vr0 = accP[mf][nf][h*2+0] - accQ[mf][nf][h*2+0];
                        float vi0 = accI[mf][nf][h*2+0];
                        float vr1 = accP[mf][nf][h*2+1] - accQ[mf][nf][h*2+1];
                        float vi1 = accI[mf][nf][h*2+1];
                        int gc = col0 + col;
                        int l0 = gc % 2049, l1 = (gc+1) % 2049;
                        float om0 = 1.5339807878856412e-3f * (float)l0;
                        float om1 = 1.5339807878856412e-3f * (float)l1;
                        float dre = -lre;
                        float di0 = om0 - lim, di1 = om1 - lim;
                        float iv0 = 1.0f/(dre*dre + di0*di0);
                        float iv1 = 1.0f/(dre*dre + di1*di1);
                        float kr0 = dre*iv0, ki0 = -di0*iv0;
                        float kr1 = dre*iv1, ki1 = -di1*iv1;
                        float tr0 = vr0*kr0 - vi0*ki0, ti0 = vr0*ki0 + vi0*kr0;
                        float tr1 = vr1*kr1 - vi1*ki1, ti1 = vr1*ki1 + vi1*kr1;
                        int off = row*USTR + col;
                        __nv_bfloat16 h0,l0b,h1,l1b;
                        split2(tr0,h0,l0b); split2(tr1,h1,l1b);
                        *reinterpret_cast<__nv_bfloat162*>(&Wb[0*UPL+off]) = __nv_bfloat162(h0,h1);
                        *reinterpret_cast<__nv_bfloat162*>(&Wb[1*UPL+off]) = __nv_bfloat162(l0b,l1b);
                        split2(ti0,h0,l0b); split2(ti1,h1,l1b);
                        *reinterpret_cast<__nv_bfloat162*>(&Wb[2*UPL+off]) = __nv_bfloat162(h0,h1);
                        *reinterpret_cast<__nv_bfloat162*>(&Wb[3*UPL+off]) = __nv_bfloat162(l0b,l1b);
                        #pragma unroll
                        for (int r=0;r<2;r++) {
                            accP[mf][nf][h*2+r]=0.f; accQ[mf][nf][h*2+r]=0.f; accI[mf][nf][h*2+r]=0.f;
                        }
                    }
                }
            }
        }
        cp_wait1();
        __syncthreads();   // chunk c data ready; Wb visible at c==4

        const __nv_bfloat16* Bbase; int krow;
        if (c < 4)       { Bbase = Ub; krow = c*32; }
        else if (c < 8)  { Bbase = Wb; krow = (c-4)*32; }
        else             { Bbase = Ub; krow = (c-8)*32; }
        const __nv_bfloat16* As = Ab + (c&1)*(4*APL2);

        // ---- preload BOTH kk halves of B fragments
        uint32_t b[2][4][4][2];
        #pragma unroll
        for (int half = 0; half < 2; half++)
            #pragma unroll
            for (int q = 0; q < 4; q++)
                #pragma unroll
                for (int np = 0; np < 2; np++) {
                    uint32_t addr = cvta_s(Bbase + q*UPL + (krow + half*16 + l16)*USTR
                                           + wn*32 + np*16 + lhi);
                    ldsm_x4t(b[half][q][2*np][0], b[half][q][2*np][1],
                             b[half][q][2*np+1][0], b[half][q][2*np+1][1], addr);
                }
        #pragma unroll
        for (int half = 0; half < 2; half++) {
            const int kk = half*16;
            #pragma unroll
            for (int p = 0; p < 4; p++) {
                uint32_t a[2][4];
                #pragma unroll
                for (int mf = 0; mf < 2; mf++) {
                    uint32_t addr = cvta_s(As + p*APL2 + (wm*32 + mf*16 + l16)*AKSTR + kk + lhi);
                    ldsm_x4(a[mf][0], a[mf][1], a[mf][2], a[mf][3], addr);
                }
                #pragma unroll
                for (int mf = 0; mf < 2; mf++)
                    #pragma unroll
                    for (int nf = 0; nf < 4; nf++) {
                        if (p == 0) {                       // ArH
                            mma_bf16(accP[mf][nf], a[mf], b[half][0][nf]);
                            mma_bf16(accP[mf][nf], a[mf], b[half][1][nf]);
                            mma_bf16(accI[mf][nf], a[mf], b[half][2][nf]);
                            mma_bf16(accI[mf][nf], a[mf], b[half][3][nf]);
                        } else if (p == 1) {                // ArL
                            mma_bf16(accP[mf][nf], a[mf], b[half][0][nf]);
                            mma_bf16(accI[mf][nf], a[mf], b[half][2][nf]);
                        } else if (p == 2) {                // AiH
                            mma_bf16(accQ[mf][nf], a[mf], b[half][2][nf]);
                            mma_bf16(accQ[mf][nf], a[mf], b[half][3][nf]);
                            mma_bf16(accI[mf][nf], a[mf], b[half][0][nf]);
                            mma_bf16(accI[mf][nf], a[mf], b[half][1][nf]);
                        } else {                            // AiL
                            mma_bf16(accQ[mf][nf], a[mf], b[half][2][nf]);
                            mma_bf16(accI[mf][nf], a[mf], b[half][0][nf]);
                        }
                    }
            }
        }
        __syncthreads();   // all warps done reading buf c&1 before restage
    }

    // ---- GEMM2 epilogue: real = P-Q, write Ys (fp32)
    #pragma unroll
    for (int mf = 0; mf < 2; mf++) {
        #pragma unroll
        for (int h = 0; h < 2; h++) {
            int row = wm*32 + mf*16 + (lane>>2) + h*8;
            #pragma unroll
            for (int nf = 0; nf < 4; nf++) {
                int col = col0 + wn*32 + nf*8 + (lane&3)*2;
                float4 o = make_float4(accP[mf][nf][h*2+0] - accQ[mf][nf][h*2+0],
                                       accI[mf][nf][h*2+0],
                                       accP[mf][nf][h*2+1] - accQ[mf][nf][h*2+1],
                                       accI[mf][nf][h*2+1]);
                *reinterpret_cast<float4*>(&g_Ys[(size_t)row*NCOLP + col]) = o;
            }
        }
    }
}

// ---------------- inverse FFT + GELU ----------------------------------------
__global__ void __launch_bounds__(512) k_fft_inv(float* __restrict__ out) {
    extern __shared__ float2 sm[];
    float2* sa = sm; float2* sb = sm+4096; float2* tw = sm+8192;
    int r0 = blockIdx.x*2;
    int b = r0 >> 7, h0 = r0 & 127;
    const float2* in0 = g_Ys + (size_t)h0*NCOLP + b*LF;
    for (int k = threadIdx.x; k < LF; k += blockDim.x) {
        float2 y1 = in0[k];
        float2 y2 = in0[NCOLP+k];
        if (k == 0 || k == 2048) { y1.y = 0.f; y2.y = 0.f; }
        sa[k] = make_float2(y1.x - y2.y, y1.y + y2.x);
        if (k > 0 && k < 2048)
            sa[4096-k] = make_float2(y1.x + y2.y, y2.x - y1.y);
    }
    for (int k = threadIdx.x; k < TWN; k += blockDim.x) {
        float s,c; sincospif(-(float)k/2048.0f,&s,&c); tw[k]=make_float2(c,s);
    }
    __syncthreads();
    stockham8(sa, sb, tw, true);
    float* o0 = out + (size_t)r0*Ld;
    const float sc = 1.0f/4096.0f;
    for (int t = threadIdx.x; t < Ld; t += blockDim.x) {
        float v0 = sa[t].x*sc, v1 = sa[t].y*sc;
        o0[t]    = 0.5f*v0*(1.0f + erff(v0*0.70710678118654752f));
        o0[t+Ld] = 0.5f*v1*(1.0f + erff(v1*0.70710678118654752f));
    }
}

// ---------------- launch ----------------------------------------------------
extern "C" void kernel_launch(void* const* d_in, const int* in_sizes, int n_in,
                              void* d_out, int out_size) {
    (void)in_sizes; (void)n_in; (void)out_size;
    const float* u   = (const float*)d_in[0];
    const float* C2  = (const float*)d_in[1];
    const float* Bb2 = (const float*)d_in[2];
    const float* Dm  = (const float*)d_in[3];
    const float* Lam = (const float*)d_in[4];
    float* out = (float*)d_out;

    cudaFuncSetAttribute(k_fft_fwd, cudaFuncAttributeMaxDynamicSharedMemorySize, FFT_SMEM);
    cudaFuncSetAttribute(k_fft_inv, cudaFuncAttributeMaxDynamicSharedMemorySize, FFT_SMEM);
    cudaFuncSetAttribute(k_fused,  cudaFuncAttributeMaxDynamicSharedMemorySize, FUSED_SMEM);

    k_fold1<<<384, 128>>>(C2, Bb2, Dm);
    k_fold2<<<128, 128>>>();
    k_fft_fwd<<<512, 512, FFT_SMEM>>>(u);
    k_fused<<<NCOLP/NT, 256, FUSED_SMEM>>>(Lam);
    k_fft_inv<<<512, 512, FFT_SMEM>>>(out);
}

// round 14
// speedup vs baseline: 1.1985x; 1.1804x over previous
#include <cuda_runtime.h>
#include <cuda_bf16.h>
#include <cstdint>

#define BSZ   8
#define Hd    128
#define Ld    4096
#define LF    2049
#define NCOL  (BSZ*LF)      /* 16392 */
#define NCOLP 16512         /* multiple of 64 */
#define NT    64            /* cols per CTA */

// ---------------- scratch (device globals: allocation-free) ----------------
__device__ __nv_bfloat16 g_AB[4][128*128];    // B~ planes: ArH ArL AiH AiL  [p][m] = A[row=p][k=m]
__device__ __nv_bfloat16 g_AE[4][128*256];    // [C~|D~] planes              [n][k]
__device__ __nv_bfloat16 g_Pb[4][128*NCOLP];  // Uhat split planes
__device__ float2 g_Ys[128*NCOLP];            // spectral output (fp32)

__device__ __forceinline__ float2 cmulf(float2 a, float2 b) {
    return make_float2(a.x*b.x - a.y*b.y, a.x*b.y + a.y*b.x);
}
__device__ __forceinline__ void split2(float v, __nv_bfloat16& h, __nv_bfloat16& l) {
    h = __float2bfloat16(v);
    l = __float2bfloat16(v - __bfloat162float(h));
}

// ---------------- Stockham radix-8, N=4096 = 8^4 ----------------------------
__device__ __forceinline__ void r4core(const float2* a, float2* o, bool inv) {
    float2 s02 = make_float2(a[0].x+a[2].x, a[0].y+a[2].y);
    float2 d02 = make_float2(a[0].x-a[2].x, a[0].y-a[2].y);
    float2 s13 = make_float2(a[1].x+a[3].x, a[1].y+a[3].y);
    float2 d13 = make_float2(a[1].x-a[3].x, a[1].y-a[3].y);
    float2 jd = inv ? make_float2(-d13.y, d13.x) : make_float2(d13.y, -d13.x);
    o[0] = make_float2(s02.x+s13.x, s02.y+s13.y);
    o[1] = make_float2(d02.x+jd.x,  d02.y+jd.y);
    o[2] = make_float2(s02.x-s13.x, s02.y-s13.y);
    o[3] = make_float2(d02.x-jd.x,  d02.y-jd.y);
}

// Radix-8 stage; twiddle table has only 512 base entries (w^j built iteratively).
// Requires blockDim.x == 512.
__device__ __forceinline__ void stockham8(float2* sa, float2* sb, const float2* tw, bool inv) {
    const float S = 0.70710678118654752f;
    float2* src = sa; float2* dst = sb;
    #pragma unroll 1
    for (int s = 0; s < 4; s++) {
        int t3 = 3*s;
        int mask = (1<<t3) - 1;
        int idx = threadIdx.x;
        int p = idx >> t3, q = idx & mask;
        int bp = p << t3;
        float2 a[8];
        #pragma unroll
        for (int m = 0; m < 8; m++) a[m] = src[q + bp + m*512];
        float2 ev[4] = {a[0],a[2],a[4],a[6]};
        float2 od[4] = {a[1],a[3],a[5],a[7]};
        float2 E[4], O[4];
        r4core(ev, E, inv);
        r4core(od, O, inv);
        float2 w81 = inv ? make_float2(S,  S) : make_float2(S, -S);
        float2 w83 = inv ? make_float2(-S, S) : make_float2(-S,-S);
        O[1] = cmulf(O[1], w81);
        O[2] = inv ? make_float2(-O[2].y, O[2].x) : make_float2(O[2].y, -O[2].x);
        O[3] = cmulf(O[3], w83);
        float2 A[8];
        #pragma unroll
        for (int j = 0; j < 4; j++) {
            A[j]   = make_float2(E[j].x+O[j].x, E[j].y+O[j].y);
            A[j+4] = make_float2(E[j].x-O[j].x, E[j].y-O[j].y);
        }
        int dbase = q + 8*bp;
        float2 w1 = tw[bp];
        if (inv) w1.y = -w1.y;
        float2 w = w1;
        dst[dbase] = A[0];
        dst[dbase + (1<<t3)] = cmulf(A[1], w);
        #pragma unroll
        for (int j = 2; j < 8; j++) {
            w = cmulf(w, w1);
            dst[dbase + (j<<t3)] = cmulf(A[j], w);
        }
        __syncthreads();
        float2* t = src; src = dst; dst = t;
    }
}

#define TWN 512
#define FFT_SMEM ((4096+4096+TWN) * (int)sizeof(float2))   /* 69632 B -> 3 CTAs/SM */

// ---------------- combined: forward FFT (blocks 0..511) + folds (512..607) --
__global__ void __launch_bounds__(512) k_fwd_prep(const float* __restrict__ u,
                                                  const float* __restrict__ C2,
                                                  const float* __restrict__ Bb2,
                                                  const float* __restrict__ Dm) {
    extern __shared__ float2 sm[];
    if (blockIdx.x < 512) {
        // ----- FFT path: 2 real rows packed into one complex FFT
        float2* sa = sm; float2* sb = sm+4096; float2* tw = sm+8192;
        int r0 = blockIdx.x*2;
        int b = r0 >> 7, h0 = r0 & 127;
        const float* u0 = u + (size_t)r0*Ld;
        for (int t = threadIdx.x; t < Ld; t += blockDim.x)
            sa[t] = make_float2(u0[t], u0[t+Ld]);
        for (int k = threadIdx.x; k < TWN; k += blockDim.x) {
            float s,c; sincospif(-(float)k/2048.0f,&s,&c); tw[k]=make_float2(c,s);
        }
        __syncthreads();
        stockham8(sa, sb, tw, false);
        size_t o1 = (size_t)h0*NCOLP + b*LF;
        size_t o2 = o1 + NCOLP;
        for (int k = threadIdx.x; k < LF; k += blockDim.x) {
            float2 zk = sa[k];
            float2 zn = sa[(4096-k)&4095];
            float2 x1 = make_float2(0.5f*(zk.x+zn.x), 0.5f*(zk.y-zn.y));
            float2 x2 = make_float2(0.5f*(zk.y+zn.y), 0.5f*(zn.x-zk.x));
            __nv_bfloat16 h, l;
            split2(x1.x,h,l); g_Pb[0][o1+k]=h; g_Pb[1][o1+k]=l;
            split2(x1.y,h,l); g_Pb[2][o1+k]=h; g_Pb[3][o1+k]=l;
            split2(x2.x,h,l); g_Pb[0][o2+k]=h; g_Pb[1][o2+k]=l;
            split2(x2.y,h,l); g_Pb[2][o2+k]=h; g_Pb[3][o2+k]=l;
        }
    } else {
        // ----- fold path: 4 rows per block, 512 threads
        float2* twH = sm;            // 128
        float2* vv  = sm + 128;      // 4*128 scratch (D~ blocks)
        int t = threadIdx.x;
        if (t < 128) { float s,c; sincospif(-(float)t/64.0f,&s,&c); twH[t]=make_float2(c,s); }
        __syncthreads();
        int grp = blockIdx.x - 512;     // 0..95
        int sub = t >> 7, inner = t & 127;
        __nv_bfloat16 h, l;
        if (grp < 32) {
            // B~[p][m] = sum_q Bb[p][q] * F[q,m]
            int p = grp*4 + sub, m = inner;
            float2 acc = make_float2(0.f,0.f);
            for (int q = 0; q < 128; q++) {
                float2 w = twH[(q*m)&127];
                float br = Bb2[(p*128+q)*2], bi = Bb2[(p*128+q)*2+1];
                acc.x += br*w.x - bi*w.y;
                acc.y += br*w.y + bi*w.x;
            }
            int idx = p*128 + m;        // [row=p][k=m]
            split2(acc.x,h,l); g_AB[0][idx]=h; g_AB[1][idx]=l;
            split2(acc.y,h,l); g_AB[2][idx]=h; g_AB[3][idx]=l;
        } else if (grp < 64) {
            // C~[n][p] = (1/H) sum_h conj(F[n,h]) * C[h][p]
            int n = (grp-32)*4 + sub, p = inner;
            float2 acc = make_float2(0.f,0.f);
            for (int hh = 0; hh < 128; hh++) {
                float2 w = twH[(n*hh)&127]; w.y = -w.y;
                float cr = C2[(hh*128+p)*2], ci = C2[(hh*128+p)*2+1];
                acc.x += cr*w.x - ci*w.y;
                acc.y += cr*w.y + ci*w.x;
            }
            acc.x *= (1.0f/128.0f); acc.y *= (1.0f/128.0f);
            int idx = n*256 + p;        // [row=n][k=p]
            split2(acc.x,h,l); g_AE[0][idx]=h; g_AE[1][idx]=l;
            split2(acc.y,h,l); g_AE[2][idx]=h; g_AE[3][idx]=l;
        } else {
            // D~[n][m] = (1/H) * (conj(F[n,:])·D) · F[:,m]   (two-phase)
            int n = (grp-64)*4 + sub;
            {   // phase 1: vv[sub][q] = sum_h conj(F[n,h]) * D[h,q]
                int q = inner;
                float2 acc = make_float2(0.f,0.f);
                for (int hh = 0; hh < 128; hh++) {
                    float2 w = twH[(n*hh)&127];
                    float d = Dm[hh*128+q];
                    acc.x += d*w.x;
                    acc.y -= d*w.y;     // conj
                }
                vv[sub*128 + q] = acc;
            }
            __syncthreads();
            {   // phase 2: D~[n][m] = (1/H) sum_q vv[sub][q] * F[q,m]
                int m = inner;
                float2 acc = make_float2(0.f,0.f);
                for (int q = 0; q < 128; q++) {
                    float2 w = twH[(q*m)&127];
                    float2 vq = vv[sub*128 + q];
                    acc.x += vq.x*w.x - vq.y*w.y;
                    acc.y += vq.x*w.y + vq.y*w.x;
                }
                acc.x *= (1.0f/128.0f); acc.y *= (1.0f/128.0f);
                int idx = n*256 + 128 + m;   // [row=n][k=128+m]
                split2(acc.x,h,l); g_AE[0][idx]=h; g_AE[1][idx]=l;
                split2(acc.y,h,l); g_AE[2][idx]=h; g_AE[3][idx]=l;
            }
        }
    }
}

// ---------------- fused tensor-core pipeline (FROZEN from round 11) ---------
// K-chunk = 32 (12 chunks: 4 GEMM1, 8 GEMM2) -> 24 barriers.
#define USTR 72
#define UPL  (128*USTR)
#define AKSTR 40
#define APL2 (128*AKSTR)
#define FUSED_SMEM ((8*UPL + 2*4*APL2) * 2)   /* 229376 bytes */

__device__ __forceinline__ uint32_t cvta_s(const void* p) {
    return (uint32_t)__cvta_generic_to_shared(p);
}
__device__ __forceinline__ void cp16(uint32_t s, const void* g) {
    asm volatile("cp.async.cg.shared.global [%0], [%1], 16;" :: "r"(s), "l"(g));
}
__device__ __forceinline__ void cp_commit() { asm volatile("cp.async.commit_group;"); }
__device__ __forceinline__ void cp_wait1()  { asm volatile("cp.async.wait_group 1;"); }
__device__ __forceinline__ void ldsm_x4(uint32_t& r0, uint32_t& r1, uint32_t& r2, uint32_t& r3,
                                        uint32_t addr) {
    asm volatile("ldmatrix.sync.aligned.m8n8.x4.shared.b16 {%0,%1,%2,%3}, [%4];"
                 : "=r"(r0), "=r"(r1), "=r"(r2), "=r"(r3) : "r"(addr));
}
__device__ __forceinline__ void ldsm_x4t(uint32_t& r0, uint32_t& r1, uint32_t& r2, uint32_t& r3,
                                         uint32_t addr) {
    asm volatile("ldmatrix.sync.aligned.m8n8.x4.trans.shared.b16 {%0,%1,%2,%3}, [%4];"
                 : "=r"(r0), "=r"(r1), "=r"(r2), "=r"(r3) : "r"(addr));
}
__device__ __forceinline__ void mma_bf16(float* c, const uint32_t* a, const uint32_t* b) {
    asm volatile("mma.sync.aligned.m16n8k16.row.col.f32.bf16.bf16.f32 "
                 "{%0,%1,%2,%3}, {%4,%5,%6,%7}, {%8,%9}, {%0,%1,%2,%3};"
                 : "+f"(c[0]), "+f"(c[1]), "+f"(c[2]), "+f"(c[3])
                 : "r"(a[0]), "r"(a[1]), "r"(a[2]), "r"(a[3]), "r"(b[0]), "r"(b[1]));
}

// 256 threads: 8 warps = 4(M) x 2(N); warp tile 32(M) x 32(N).
// Accumulators: P = Ar*Br, Q = Ai*Bi, I = Ar*Bi + Ai*Br;  real = P - Q.
__global__ void __launch_bounds__(256, 1) k_fused(const float* __restrict__ Lam) {
    extern __shared__ __nv_bfloat16 smem[];
    __nv_bfloat16* Ub = smem;                 // 4 planes
    __nv_bfloat16* Wb = smem + 4*UPL;         // 4 planes
    __nv_bfloat16* Ab = smem + 8*UPL;         // 2 bufs x 4 planes

    const int tid  = threadIdx.x;
    const int warp = tid >> 5, lane = tid & 31;
    const int wm = warp & 3, wn = warp >> 2;      // 4 warps down M, 2 across N
    const int col0 = blockIdx.x*NT;
    const int l16 = lane & 15, lhi = (lane >> 4) << 3;

    float accP[2][4][4], accQ[2][4][4], accI[2][4][4];
    #pragma unroll
    for (int mf=0;mf<2;mf++)
        #pragma unroll
        for (int nf=0;nf<4;nf++)
            #pragma unroll
            for (int r=0;r<4;r++) { accP[mf][nf][r]=0.f; accQ[mf][nf][r]=0.f; accI[mf][nf][r]=0.f; }

    auto stageU = [&]() {
        #pragma unroll
        for (int i = 0; i < 16; i++) {
            int idx = tid + i*256;
            int pl = idx >> 10, rem = idx & 1023;
            int row = rem >> 3, c = rem & 7;
            cp16(cvta_s(Ub + pl*UPL + row*USTR + c*8),
                 g_Pb[pl] + (size_t)row*NCOLP + col0 + c*8);
        }
    };
    auto stageA = [&](int cc) {
        const __nv_bfloat16* Asrc;
        int ks, aplg, k0;
        if (cc < 4) { Asrc = g_AB[0]; ks = 128; aplg = 128*128; k0 = cc*32; }
        else        { Asrc = g_AE[0]; ks = 256; aplg = 128*256; k0 = (cc-4)*32; }
        __nv_bfloat16* dst = Ab + (cc&1)*(4*APL2);
        #pragma unroll
        for (int i = 0; i < 8; i++) {
            int idx = tid + i*256;
            int pl = idx >> 9, rem = idx & 511;
            int row = rem >> 2, c = rem & 3;
            cp16(cvta_s(dst + pl*APL2 + row*AKSTR + c*8),
                 Asrc + (size_t)pl*aplg + (size_t)row*ks + k0 + c*8);
        }
    };

    stageU(); stageA(0); cp_commit();

    #pragma unroll 1
    for (int c = 0; c < 12; c++) {
        if (c+1 < 12) stageA(c+1);
        cp_commit();

        if (c == 4) {
            #pragma unroll
            for (int mf = 0; mf < 2; mf++) {
                #pragma unroll
                for (int h = 0; h < 2; h++) {
                    int row = wm*32 + mf*16 + (lane>>2) + h*8;
                    float lre = Lam[2*row], lim = Lam[2*row+1];
                    #pragma unroll
                    for (int nf = 0; nf < 4; nf++) {
                        int col = wn*32 + nf*8 + (lane&3)*2;
                        float vr0 = accP[mf][nf][h*2+0] - accQ[mf][nf][h*2+0];
                        float vi0 = accI[mf][nf][h*2+0];
                        float vr1 = accP[mf][nf][h*2+1] - accQ[mf][nf][h*2+1];
                        float vi1 = accI[mf][nf][h*2+1];
                        int gc = col0 + col;
                        int l0 = gc % 2049, l1 = (gc+1) % 2049;
                        float om0 = 1.5339807878856412e-3f * (float)l0;
                        float om1 = 1.5339807878856412e-3f * (float)l1;
                        float dre = -lre;
                        float di0 = om0 - lim, di1 = om1 - lim;
                        float iv0 = 1.0f/(dre*dre + di0*di0);
                        float iv1 = 1.0f/(dre*dre + di1*di1);
                        float kr0 = dre*iv0, ki0 = -di0*iv0;
                        float kr1 = dre*iv1, ki1 = -di1*iv1;
                        float tr0 = vr0*kr0 - vi0*ki0, ti0 = vr0*ki0 + vi0*kr0;
                        float tr1 = vr1*kr1 - vi1*ki1, ti1 = vr1*ki1 + vi1*kr1;
                        int off = row*USTR + col;
                        __nv_bfloat16 h0,l0b,h1,l1b;
                        split2(tr0,h0,l0b); split2(tr1,h1,l1b);
                        *reinterpret_cast<__nv_bfloat162*>(&Wb[0*UPL+off]) = __nv_bfloat162(h0,h1);
                        *reinterpret_cast<__nv_bfloat162*>(&Wb[1*UPL+off]) = __nv_bfloat162(l0b,l1b);
                        split2(ti0,h0,l0b); split2(ti1,h1,l1b);
                        *reinterpret_cast<__nv_bfloat162*>(&Wb[2*UPL+off]) = __nv_bfloat162(h0,h1);
                        *reinterpret_cast<__nv_bfloat162*>(&Wb[3*UPL+off]) = __nv_bfloat162(l0b,l1b);
                        #pragma unroll
                        for (int r=0;r<2;r++) {
                            accP[mf][nf][h*2+r]=0.f; accQ[mf][nf][h*2+r]=0.f; accI[mf][nf][h*2+r]=0.f;
                        }
                    }
                }
            }
        }
        cp_wait1();
        __syncthreads();

        const __nv_bfloat16* Bbase; int krow;
        if (c < 4)       { Bbase = Ub; krow = c*32; }
        else if (c < 8)  { Bbase = Wb; krow = (c-4)*32; }
        else             { Bbase = Ub; krow = (c-8)*32; }
        const __nv_bfloat16* As = Ab + (c&1)*(4*APL2);

        uint32_t b[2][4][4][2];
        #pragma unroll
        for (int half = 0; half < 2; half++)
            #pragma unroll
            for (int q = 0; q < 4; q++)
                #pragma unroll
                for (int np = 0; np < 2; np++) {
                    uint32_t addr = cvta_s(Bbase + q*UPL + (krow + half*16 + l16)*USTR
                                           + wn*32 + np*16 + lhi);
                    ldsm_x4t(b[half][q][2*np][0], b[half][q][2*np][1],
                             b[half][q][2*np+1][0], b[half][q][2*np+1][1], addr);
                }
        #pragma unroll
        for (int half = 0; half < 2; half++) {
            const int kk = half*16;
            #pragma unroll
            for (int p = 0; p < 4; p++) {
                uint32_t a[2][4];
                #pragma unroll
                for (int mf = 0; mf < 2; mf++) {
                    uint32_t addr = cvta_s(As + p*APL2 + (wm*32 + mf*16 + l16)*AKSTR + kk + lhi);
                    ldsm_x4(a[mf][0], a[mf][1], a[mf][2], a[mf][3], addr);
                }
                #pragma unroll
                for (int mf = 0; mf < 2; mf++)
                    #pragma unroll
                    for (int nf = 0; nf < 4; nf++) {
                        if (p == 0) {
                            mma_bf16(accP[mf][nf], a[mf], b[half][0][nf]);
                            mma_bf16(accP[mf][nf], a[mf], b[half][1][nf]);
                            mma_bf16(accI[mf][nf], a[mf], b[half][2][nf]);
                            mma_bf16(accI[mf][nf], a[mf], b[half][3][nf]);
                        } else if (p == 1) {
                            mma_bf16(accP[mf][nf], a[mf], b[half][0][nf]);
                            mma_bf16(accI[mf][nf], a[mf], b[half][2][nf]);
                        } else if (p == 2) {
                            mma_bf16(accQ[mf][nf], a[mf], b[half][2][nf]);
                            mma_bf16(accQ[mf][nf], a[mf], b[half][3][nf]);
                            mma_bf16(accI[mf][nf], a[mf], b[half][0][nf]);
                            mma_bf16(accI[mf][nf], a[mf], b[half][1][nf]);
                        } else {
                            mma_bf16(accQ[mf][nf], a[mf], b[half][2][nf]);
                            mma_bf16(accI[mf][nf], a[mf], b[half][0][nf]);
                        }
                    }
            }
        }
        __syncthreads();
    }

    #pragma unroll
    for (int mf = 0; mf < 2; mf++) {
        #pragma unroll
        for (int h = 0; h < 2; h++) {
            int row = wm*32 + mf*16 + (lane>>2) + h*8;
            #pragma unroll
            for (int nf = 0; nf < 4; nf++) {
                int col = col0 + wn*32 + nf*8 + (lane&3)*2;
                float4 o = make_float4(accP[mf][nf][h*2+0] - accQ[mf][nf][h*2+0],
                                       accI[mf][nf][h*2+0],
                                       accP[mf][nf][h*2+1] - accQ[mf][nf][h*2+1],
                                       accI[mf][nf][h*2+1]);
                *reinterpret_cast<float4*>(&g_Ys[(size_t)row*NCOLP + col]) = o;
            }
        }
    }
}

// ---------------- inverse FFT + GELU ----------------------------------------
__global__ void __launch_bounds__(512) k_fft_inv(float* __restrict__ out) {
    extern __shared__ float2 sm[];
    float2* sa = sm; float2* sb = sm+4096; float2* tw = sm+8192;
    int r0 = blockIdx.x*2;
    int b = r0 >> 7, h0 = r0 & 127;
    const float2* in0 = g_Ys + (size_t)h0*NCOLP + b*LF;
    for (int k = threadIdx.x; k < LF; k += blockDim.x) {
        float2 y1 = in0[k];
        float2 y2 = in0[NCOLP+k];
        if (k == 0 || k == 2048) { y1.y = 0.f; y2.y = 0.f; }
        sa[k] = make_float2(y1.x - y2.y, y1.y + y2.x);
        if (k > 0 && k < 2048)
            sa[4096-k] = make_float2(y1.x + y2.y, y2.x - y1.y);
    }
    for (int k = threadIdx.x; k < TWN; k += blockDim.x) {
        float s,c; sincospif(-(float)k/2048.0f,&s,&c); tw[k]=make_float2(c,s);
    }
    __syncthreads();
    stockham8(sa, sb, tw, true);
    float* o0 = out + (size_t)r0*Ld;
    const float sc = 1.0f/4096.0f;
    for (int t = threadIdx.x; t < Ld; t += blockDim.x) {
        float v0 = sa[t].x*sc, v1 = sa[t].y*sc;
        o0[t]    = 0.5f*v0*(1.0f + erff(v0*0.70710678118654752f));
        o0[t+Ld] = 0.5f*v1*(1.0f + erff(v1*0.70710678118654752f));
    }
}

// ---------------- launch ----------------------------------------------------
extern "C" void kernel_launch(void* const* d_in, const int* in_sizes, int n_in,
                              void* d_out, int out_size) {
    (void)in_sizes; (void)n_in; (void)out_size;
    const float* u   = (const float*)d_in[0];
    const float* C2  = (const float*)d_in[1];
    const float* Bb2 = (const float*)d_in[2];
    const float* Dm  = (const float*)d_in[3];
    const float* Lam = (const float*)d_in[4];
    float* out = (float*)d_out;

    cudaFuncSetAttribute(k_fwd_prep, cudaFuncAttributeMaxDynamicSharedMemorySize, FFT_SMEM);
    cudaFuncSetAttribute(k_fft_inv,  cudaFuncAttributeMaxDynamicSharedMemorySize, FFT_SMEM);
    cudaFuncSetAttribute(k_fused,    cudaFuncAttributeMaxDynamicSharedMemorySize, FUSED_SMEM);

    k_fwd_prep<<<608, 512, FFT_SMEM>>>(u, C2, Bb2, Dm);
    k_fused<<<NCOLP/NT, 256, FUSED_SMEM>>>(Lam);
    k_fft_inv<<<512, 512, FFT_SMEM>>>(out);
}

// round 16
// speedup vs baseline: 1.2203x; 1.0182x over previous
#include <cuda_runtime.h>
#include <cuda_bf16.h>
#include <cstdint>

#define BSZ   8
#define Hd    128
#define Ld    4096
#define LF    2049
#define NCOL  (BSZ*LF)      /* 16392 */
#define NCOLP 16512         /* multiple of 64 */
#define NT    64            /* cols per CTA */

// ---------------- scratch (device globals: allocation-free) ----------------
__device__ __nv_bfloat16 g_AB[4][128*128];    // B~ planes: ArH ArL AiH AiL  [p][m]
__device__ __nv_bfloat16 g_AE[4][128*256];    // [C~|D~] planes              [n][k]
__device__ __nv_bfloat16 g_Pb[4][128*NCOLP];  // Uhat split planes
__device__ float2 g_Ys[128*NCOLP];            // spectral output (fp32)

__device__ __forceinline__ float2 cmulf(float2 a, float2 b) {
    return make_float2(a.x*b.x - a.y*b.y, a.x*b.y + a.y*b.x);
}
__device__ __forceinline__ void split2(float v, __nv_bfloat16& h, __nv_bfloat16& l) {
    h = __float2bfloat16(v);
    l = __float2bfloat16(v - __bfloat162float(h));
}
// smem swizzle for FFT arrays: bijection on [0,4096), spreads strided stores
__device__ __forceinline__ int FSW(int i) { return i ^ ((i >> 4) & 15); }

// ---------------- Stockham radix-8, N=4096 = 8^4 ----------------------------
__device__ __forceinline__ void r4core(const float2* a, float2* o, bool inv) {
    float2 s02 = make_float2(a[0].x+a[2].x, a[0].y+a[2].y);
    float2 d02 = make_float2(a[0].x-a[2].x, a[0].y-a[2].y);
    float2 s13 = make_float2(a[1].x+a[3].x, a[1].y+a[3].y);
    float2 d13 = make_float2(a[1].x-a[3].x, a[1].y-a[3].y);
    float2 jd = inv ? make_float2(-d13.y, d13.x) : make_float2(d13.y, -d13.x);
    o[0] = make_float2(s02.x+s13.x, s02.y+s13.y);
    o[1] = make_float2(d02.x+jd.x,  d02.y+jd.y);
    o[2] = make_float2(s02.x-s13.x, s02.y-s13.y);
    o[3] = make_float2(d02.x-jd.x,  d02.y-jd.y);
}

// Radix-8 stage; 512-entry twiddle table, higher powers built iteratively.
// All sa/sb accesses go through FSW(). Requires blockDim.x == 512.
__device__ __forceinline__ void stockham8(float2* sa, float2* sb, const float2* tw, bool inv) {
    const float S = 0.70710678118654752f;
    float2* src = sa; float2* dst = sb;
    #pragma unroll 1
    for (int s = 0; s < 4; s++) {
        int t3 = 3*s;
        int mask = (1<<t3) - 1;
        int idx = threadIdx.x;
        int p = idx >> t3, q = idx & mask;
        int bp = p << t3;
        float2 a[8];
        #pragma unroll
        for (int m = 0; m < 8; m++) a[m] = src[FSW(q + bp + m*512)];
        float2 ev[4] = {a[0],a[2],a[4],a[6]};
        float2 od[4] = {a[1],a[3],a[5],a[7]};
        float2 E[4], O[4];
        r4core(ev, E, inv);
        r4core(od, O, inv);
        float2 w81 = inv ? make_float2(S,  S) : make_float2(S, -S);
        float2 w83 = inv ? make_float2(-S, S) : make_float2(-S,-S);
        O[1] = cmulf(O[1], w81);
        O[2] = inv ? make_float2(-O[2].y, O[2].x) : make_float2(O[2].y, -O[2].x);
        O[3] = cmulf(O[3], w83);
        float2 A[8];
        #pragma unroll
        for (int j = 0; j < 4; j++) {
            A[j]   = make_float2(E[j].x+O[j].x, E[j].y+O[j].y);
            A[j+4] = make_float2(E[j].x-O[j].x, E[j].y-O[j].y);
        }
        int dbase = q + 8*bp;
        float2 w1 = tw[bp];
        if (inv) w1.y = -w1.y;
        float2 w = w1;
        dst[FSW(dbase)] = A[0];
        dst[FSW(dbase + (1<<t3))] = cmulf(A[1], w);
        #pragma unroll
        for (int j = 2; j < 8; j++) {
            w = cmulf(w, w1);
            dst[FSW(dbase + (j<<t3))] = cmulf(A[j], w);
        }
        __syncthreads();
        float2* t = src; src = dst; dst = t;
    }
}

#define TWN 512
#define FFT_SMEM ((4096+4096+TWN) * (int)sizeof(float2))   /* 69632 B -> 3 CTAs/SM */

// ---------------- combined: forward FFT (blocks 0..511) + folds (512..607) --
__global__ void __launch_bounds__(512) k_fwd_prep(const float* __restrict__ u,
                                                  const float* __restrict__ C2,
                                                  const float* __restrict__ Bb2,
                                                  const float* __restrict__ Dm) {
    extern __shared__ float2 sm[];
    if (blockIdx.x < 512) {
        float2* sa = sm; float2* sb = sm+4096; float2* tw = sm+8192;
        int r0 = blockIdx.x*2;
        int b = r0 >> 7, h0 = r0 & 127;
        const float* u0 = u + (size_t)r0*Ld;
        for (int t = threadIdx.x; t < Ld; t += blockDim.x)
            sa[FSW(t)] = make_float2(u0[t], u0[t+Ld]);
        for (int k = threadIdx.x; k < TWN; k += blockDim.x) {
            float s,c; sincospif(-(float)k/2048.0f,&s,&c); tw[k]=make_float2(c,s);
        }
        __syncthreads();
        stockham8(sa, sb, tw, false);
        size_t o1 = (size_t)h0*NCOLP + b*LF;
        size_t o2 = o1 + NCOLP;
        for (int k = threadIdx.x; k < LF; k += blockDim.x) {
            float2 zk = sa[FSW(k)];
            float2 zn = sa[FSW((4096-k)&4095)];
            float2 x1 = make_float2(0.5f*(zk.x+zn.x), 0.5f*(zk.y-zn.y));
            float2 x2 = make_float2(0.5f*(zk.y+zn.y), 0.5f*(zn.x-zk.x));
            __nv_bfloat16 h, l;
            split2(x1.x,h,l); g_Pb[0][o1+k]=h; g_Pb[1][o1+k]=l;
            split2(x1.y,h,l); g_Pb[2][o1+k]=h; g_Pb[3][o1+k]=l;
            split2(x2.x,h,l); g_Pb[0][o2+k]=h; g_Pb[1][o2+k]=l;
            split2(x2.y,h,l); g_Pb[2][o2+k]=h; g_Pb[3][o2+k]=l;
        }
    } else {
        // ----- fold path: 4 rows per block, 512 threads
        float2* twH = sm;            // 128
        float2* vv  = sm + 128;      // 4*128 scratch (D~ blocks)
        int t = threadIdx.x;
        if (t < 128) { float s,c; sincospif(-(float)t/64.0f,&s,&c); twH[t]=make_float2(c,s); }
        __syncthreads();
        int grp = blockIdx.x - 512;     // 0..95
        int sub = t >> 7, inner = t & 127;
        __nv_bfloat16 h, l;
        if (grp < 32) {
            int p = grp*4 + sub, m = inner;
            float2 acc = make_float2(0.f,0.f);
            for (int q = 0; q < 128; q++) {
                float2 w = twH[(q*m)&127];
                float br = Bb2[(p*128+q)*2], bi = Bb2[(p*128+q)*2+1];
                acc.x += br*w.x - bi*w.y;
                acc.y += br*w.y + bi*w.x;
            }
            int idx = p*128 + m;        // [row=p][k=m]
            split2(acc.x,h,l); g_AB[0][idx]=h; g_AB[1][idx]=l;
            split2(acc.y,h,l); g_AB[2][idx]=h; g_AB[3][idx]=l;
        } else if (grp < 64) {
            int n = (grp-32)*4 + sub, p = inner;
            float2 acc = make_float2(0.f,0.f);
            for (int hh = 0; hh < 128; hh++) {
                float2 w = twH[(n*hh)&127]; w.y = -w.y;
                float cr = C2[(hh*128+p)*2], ci = C2[(hh*128+p)*2+1];
                acc.x += cr*w.x - ci*w.y;
                acc.y += cr*w.y + ci*w.x;
            }
            acc.x *= (1.0f/128.0f); acc.y *= (1.0f/128.0f);
            int idx = n*256 + p;        // [row=n][k=p]
            split2(acc.x,h,l); g_AE[0][idx]=h; g_AE[1][idx]=l;
            split2(acc.y,h,l); g_AE[2][idx]=h; g_AE[3][idx]=l;
        } else {
            int n = (grp-64)*4 + sub;
            {   // phase 1: vv[sub][q] = sum_h conj(F[n,h]) * D[h,q]
                int q = inner;
                float2 acc = make_float2(0.f,0.f);
                for (int hh = 0; hh < 128; hh++) {
                    float2 w = twH[(n*hh)&127];
                    float d = Dm[hh*128+q];
                    acc.x += d*w.x;
                    acc.y -= d*w.y;
                }
                vv[sub*128 + q] = acc;
            }
            __syncthreads();
            {   // phase 2: D~[n][m] = (1/H) sum_q vv[sub][q] * F[q,m]
                int m = inner;
                float2 acc = make_float2(0.f,0.f);
                for (int q = 0; q < 128; q++) {
                    float2 w = twH[(q*m)&127];
                    float2 vq = vv[sub*128 + q];
                    acc.x += vq.x*w.x - vq.y*w.y;
                    acc.y += vq.x*w.y + vq.y*w.x;
                }
                acc.x *= (1.0f/128.0f); acc.y *= (1.0f/128.0f);
                int idx = n*256 + 128 + m;   // [row=n][k=128+m]
                split2(acc.x,h,l); g_AE[0][idx]=h; g_AE[1][idx]=l;
                split2(acc.y,h,l); g_AE[2][idx]=h; g_AE[3][idx]=l;
            }
        }
    }
}

// ---------------- fused tensor-core pipeline (FROZEN from round 11) ---------
#define USTR 72
#define UPL  (128*USTR)
#define AKSTR 40
#define APL2 (128*AKSTR)
#define FUSED_SMEM ((8*UPL + 2*4*APL2) * 2)   /* 229376 bytes */

__device__ __forceinline__ uint32_t cvta_s(const void* p) {
    return (uint32_t)__cvta_generic_to_shared(p);
}
__device__ __forceinline__ void cp16(uint32_t s, const void* g) {
    asm volatile("cp.async.cg.shared.global [%0], [%1], 16;" :: "r"(s), "l"(g));
}
__device__ __forceinline__ void cp_commit() { asm volatile("cp.async.commit_group;"); }
__device__ __forceinline__ void cp_wait1()  { asm volatile("cp.async.wait_group 1;"); }
__device__ __forceinline__ void ldsm_x4(uint32_t& r0, uint32_t& r1, uint32_t& r2, uint32_t& r3,
                                        uint32_t addr) {
    asm volatile("ldmatrix.sync.aligned.m8n8.x4.shared.b16 {%0,%1,%2,%3}, [%4];"
                 : "=r"(r0), "=r"(r1), "=r"(r2), "=r"(r3) : "r"(addr));
}
__device__ __forceinline__ void ldsm_x4t(uint32_t& r0, uint32_t& r1, uint32_t& r2, uint32_t& r3,
                                         uint32_t addr) {
    asm volatile("ldmatrix.sync.aligned.m8n8.x4.trans.shared.b16 {%0,%1,%2,%3}, [%4];"
                 : "=r"(r0), "=r"(r1), "=r"(r2), "=r"(r3) : "r"(addr));
}
__device__ __forceinline__ void mma_bf16(float* c, const uint32_t* a, const uint32_t* b) {
    asm volatile("mma.sync.aligned.m16n8k16.row.col.f32.bf16.bf16.f32 "
                 "{%0,%1,%2,%3}, {%4,%5,%6,%7}, {%8,%9}, {%0,%1,%2,%3};"
                 : "+f"(c[0]), "+f"(c[1]), "+f"(c[2]), "+f"(c[3])
                 : "r"(a[0]), "r"(a[1]), "r"(a[2]), "r"(a[3]), "r"(b[0]), "r"(b[1]));
}

__global__ void __launch_bounds__(256, 1) k_fused(const float* __restrict__ Lam) {
    extern __shared__ __nv_bfloat16 smem[];
    __nv_bfloat16* Ub = smem;
    __nv_bfloat16* Wb = smem + 4*UPL;
    __nv_bfloat16* Ab = smem + 8*UPL;

    const int tid  = threadIdx.x;
    const int warp = tid >> 5, lane = tid & 31;
    const int wm = warp & 3, wn = warp >> 2;
    const int col0 = blockIdx.x*NT;
    const int l16 = lane & 15, lhi = (lane >> 4) << 3;

    float accP[2][4][4], accQ[2][4][4], accI[2][4][4];
    #pragma unroll
    for (int mf=0;mf<2;mf++)
        #pragma unroll
        for (int nf=0;nf<4;nf++)
            #pragma unroll
            for (int r=0;r<4;r++) { accP[mf][nf][r]=0.f; accQ[mf][nf][r]=0.f; accI[mf][nf][r]=0.f; }

    auto stageU = [&]() {
        #pragma unroll
        for (int i = 0; i < 16; i++) {
            int idx = tid + i*256;
            int pl = idx >> 10, rem = idx & 1023;
            int row = rem >> 3, c = rem & 7;
            cp16(cvta_s(Ub + pl*UPL + row*USTR + c*8),
                 g_Pb[pl] + (size_t)row*NCOLP + col0 + c*8);
        }
    };
    auto stageA = [&](int cc) {
        const __nv_bfloat16* Asrc;
        int ks, aplg, k0;
        if (cc < 4) { Asrc = g_AB[0]; ks = 128; aplg = 128*128; k0 = cc*32; }
        else        { Asrc = g_AE[0]; ks = 256; aplg = 128*256; k0 = (cc-4)*32; }
        __nv_bfloat16* dst = Ab + (cc&1)*(4*APL2);
        #pragma unroll
        for (int i = 0; i < 8; i++) {
            int idx = tid + i*256;
            int pl = idx >> 9, rem = idx & 511;
            int row = rem >> 2, c = rem & 3;
            cp16(cvta_s(dst + pl*APL2 + row*AKSTR + c*8),
                 Asrc + (size_t)pl*aplg + (size_t)row*ks + k0 + c*8);
        }
    };

    stageU(); stageA(0); cp_commit();

    #pragma unroll 1
    for (int c = 0; c < 12; c++) {
        if (c+1 < 12) stageA(c+1);
        cp_commit();

        if (c == 4) {
            #pragma unroll
            for (int mf = 0; mf < 2; mf++) {
                #pragma unroll
                for (int h = 0; h < 2; h++) {
                    int row = wm*32 + mf*16 + (lane>>2) + h*8;
                    float lre = Lam[2*row], lim = Lam[2*row+1];
                    #pragma unroll
                    for (int nf = 0; nf < 4; nf++) {
                        int col = wn*32 + nf*8 + (lane&3)*2;
                        float vr0 = accP[mf][nf][h*2+0] - accQ[mf][nf][h*2+0];
                        float vi0 = accI[mf][nf][h*2+0];
                        float vr1 = accP[mf][nf][h*2+1] - accQ[mf][nf][h*2+1];
                        float vi1 = accI[mf][nf][h*2+1];
                        int gc = col0 + col;
                        int l0 = gc % 2049, l1 = (gc+1) % 2049;
                        float om0 = 1.5339807878856412e-3f * (float)l0;
                        float om1 = 1.5339807878856412e-3f * (float)l1;
                        float dre = -lre;
                        float di0 = om0 - lim, di1 = om1 - lim;
                        float iv0 = 1.0f/(dre*dre + di0*di0);
                        float iv1 = 1.0f/(dre*dre + di1*di1);
                        float kr0 = dre*iv0, ki0 = -di0*iv0;
                        float kr1 = dre*iv1, ki1 = -di1*iv1;
                        float tr0 = vr0*kr0 - vi0*ki0, ti0 = vr0*ki0 + vi0*kr0;
                        float tr1 = vr1*kr1 - vi1*ki1, ti1 = vr1*ki1 + vi1*kr1;
                        int off = row*USTR + col;
                        __nv_bfloat16 h0,l0b,h1,l1b;
                        split2(tr0,h0,l0b); split2(tr1,h1,l1b);
                        *reinterpret_cast<__nv_bfloat162*>(&Wb[0*UPL+off]) = __nv_bfloat162(h0,h1);
                        *reinterpret_cast<__nv_bfloat162*>(&Wb[1*UPL+off]) = __nv_bfloat162(l0b,l1b);
                        split2(ti0,h0,l0b); split2(ti1,h1,l1b);
                        *reinterpret_cast<__nv_bfloat162*>(&Wb[2*UPL+off]) = __nv_bfloat162(h0,h1);
                        *reinterpret_cast<__nv_bfloat162*>(&Wb[3*UPL+off]) = __nv_bfloat162(l0b,l1b);
                        #pragma unroll
                        for (int r=0;r<2;r++) {
                            accP[mf][nf][h*2+r]=0.f; accQ[mf][nf][h*2+r]=0.f; accI[mf][nf][h*2+r]=0.f;
                        }
                    }
                }
            }
        }
        cp_wait1();
        __syncthreads();

        const __nv_bfloat16* Bbase; int krow;
        if (c < 4)       { Bbase = Ub; krow = c*32; }
        else if (c < 8)  { Bbase = Wb; krow = (c-4)*32; }
        else             { Bbase = Ub; krow = (c-8)*32; }
        const __nv_bfloat16* As = Ab + (c&1)*(4*APL2);

        uint32_t b[2][4][4][2];
        #pragma unroll
        for (int half = 0; half < 2; half++)
            #pragma unroll
            for (int q = 0; q < 4; q++)
                #pragma unroll
                for (int np = 0; np < 2; np++) {
                    uint32_t addr = cvta_s(Bbase + q*UPL + (krow + half*16 + l16)*USTR
                                           + wn*32 + np*16 + lhi);
                    ldsm_x4t(b[half][q][2*np][0], b[half][q][2*np][1],
                             b[half][q][2*np+1][0], b[half][q][2*np+1][1], addr);
                }
        #pragma unroll
        for (int half = 0; half < 2; half++) {
            const int kk = half*16;
            #pragma unroll
            for (int p = 0; p < 4; p++) {
                uint32_t a[2][4];
                #pragma unroll
                for (int mf = 0; mf < 2; mf++) {
                    uint32_t addr = cvta_s(As + p*APL2 + (wm*32 + mf*16 + l16)*AKSTR + kk + lhi);
                    ldsm_x4(a[mf][0], a[mf][1], a[mf][2], a[mf][3], addr);
                }
                #pragma unroll
                for (int mf = 0; mf < 2; mf++)
                    #pragma unroll
                    for (int nf = 0; nf < 4; nf++) {
                        if (p == 0) {
                            mma_bf16(accP[mf][nf], a[mf], b[half][0][nf]);
                            mma_bf16(accP[mf][nf], a[mf], b[half][1][nf]);
                            mma_bf16(accI[mf][nf], a[mf], b[half][2][nf]);
                            mma_bf16(accI[mf][nf], a[mf], b[half][3][nf]);
                        } else if (p == 1) {
                            mma_bf16(accP[mf][nf], a[mf], b[half][0][nf]);
                            mma_bf16(accI[mf][nf], a[mf], b[half][2][nf]);
                        } else if (p == 2) {
                            mma_bf16(accQ[mf][nf], a[mf], b[half][2][nf]);
                            mma_bf16(accQ[mf][nf], a[mf], b[half][3][nf]);
                            mma_bf16(accI[mf][nf], a[mf], b[half][0][nf]);
                            mma_bf16(accI[mf][nf], a[mf], b[half][1][nf]);
                        } else {
                            mma_bf16(accQ[mf][nf], a[mf], b[half][2][nf]);
                            mma_bf16(accI[mf][nf], a[mf], b[half][0][nf]);
                        }
                    }
            }
        }
        __syncthreads();
    }

    #pragma unroll
    for (int mf = 0; mf < 2; mf++) {
        #pragma unroll
        for (int h = 0; h < 2; h++) {
            int row = wm*32 + mf*16 + (lane>>2) + h*8;
            #pragma unroll
            for (int nf = 0; nf < 4; nf++) {
                int col = col0 + wn*32 + nf*8 + (lane&3)*2;
                float4 o = make_float4(accP[mf][nf][h*2+0] - accQ[mf][nf][h*2+0],
                                       accI[mf][nf][h*2+0],
                                       accP[mf][nf][h*2+1] - accQ[mf][nf][h*2+1],
                                       accI[mf][nf][h*2+1]);
                *reinterpret_cast<float4*>(&g_Ys[(size_t)row*NCOLP + col]) = o;
            }
        }
    }
}

// ---------------- inverse FFT + GELU ----------------------------------------
__global__ void __launch_bounds__(512) k_fft_inv(float* __restrict__ out) {
    extern __shared__ float2 sm[];
    float2* sa = sm; float2* sb = sm+4096; float2* tw = sm+8192;
    int r0 = blockIdx.x*2;
    int b = r0 >> 7, h0 = r0 & 127;
    const float2* in0 = g_Ys + (size_t)h0*NCOLP + b*LF;
    for (int k = threadIdx.x; k < LF; k += blockDim.x) {
        float2 y1 = in0[k];
        float2 y2 = in0[NCOLP+k];
        if (k == 0 || k == 2048) { y1.y = 0.f; y2.y = 0.f; }
        sa[FSW(k)] = make_float2(y1.x - y2.y, y1.y + y2.x);
        if (k > 0 && k < 2048)
            sa[FSW(4096-k)] = make_float2(y1.x + y2.y, y2.x - y1.y);
    }
    for (int k = threadIdx.x; k < TWN; k += blockDim.x) {
        float s,c; sincospif(-(float)k/2048.0f,&s,&c); tw[k]=make_float2(c,s);
    }
    __syncthreads();
    stockham8(sa, sb, tw, true);
    float* o0 = out + (size_t)r0*Ld;
    const float sc = 1.0f/4096.0f;
    for (int t = threadIdx.x; t < Ld; t += blockDim.x) {
        float2 v = sa[FSW(t)];
        float v0 = v.x*sc, v1 = v.y*sc;
        o0[t]    = 0.5f*v0*(1.0f + erff(v0*0.70710678118654752f));
        o0[t+Ld] = 0.5f*v1*(1.0f + erff(v1*0.70710678118654752f));
    }
}

// ---------------- launch ----------------------------------------------------
extern "C" void kernel_launch(void* const* d_in, const int* in_sizes, int n_in,
                              void* d_out, int out_size) {
    (void)in_sizes; (void)n_in; (void)out_size;
    const float* u   = (const float*)d_in[0];
    const float* C2  = (const float*)d_in[1];
    const float* Bb2 = (const float*)d_in[2];
    const float* Dm  = (const float*)d_in[3];
    const float* Lam = (const float*)d_in[4];
    float* out = (float*)d_out;

    cudaFuncSetAttribute(k_fwd_prep, cudaFuncAttributeMaxDynamicSharedMemorySize, FFT_SMEM);
    cudaFuncSetAttribute(k_fft_inv,  cudaFuncAttributeMaxDynamicSharedMemorySize, FFT_SMEM);
    cudaFuncSetAttribute(k_fused,    cudaFuncAttributeMaxDynamicSharedMemorySize, FUSED_SMEM);

    k_fwd_prep<<<608, 512, FFT_SMEM>>>(u, C2, Bb2, Dm);
    k_fused<<<NCOLP/NT, 256, FUSED_SMEM>>>(Lam);
    k_fft_inv<<<512, 512, FFT_SMEM>>>(out);
}

// round 17
// speedup vs baseline: 1.2478x; 1.0225x over previous
#include <cuda_runtime.h>
#include <cuda_bf16.h>
#include <cstdint>

#define BSZ   8
#define Hd    128
#define Ld    4096
#define LF    2049
#define NCOL  (BSZ*LF)      /* 16392 */
#define NCOLP 16512         /* multiple of 64 */
#define NT    64            /* cols per CTA */

// ---------------- scratch (device globals: allocation-free) ----------------
__device__ __nv_bfloat16 g_AB[4][128*128];    // B~ planes: ArH ArL AiH AiL  [p][m]
__device__ __nv_bfloat16 g_AE[4][128*256];    // [C~|D~] planes              [n][k]
__device__ __nv_bfloat16 g_Pb[4][128*NCOLP];  // Uhat split planes
__device__ float2 g_Ys[128*NCOLP];            // spectral output (fp32)

__device__ __forceinline__ float2 cmulf(float2 a, float2 b) {
    return make_float2(a.x*b.x - a.y*b.y, a.x*b.y + a.y*b.x);
}
__device__ __forceinline__ void split2(float v, __nv_bfloat16& h, __nv_bfloat16& l) {
    h = __float2bfloat16(v);
    l = __float2bfloat16(v - __bfloat162float(h));
}
// smem swizzle for FFT arrays: bijection on [0,4096), spreads strided stores
__device__ __forceinline__ int FSW(int i) { return i ^ ((i >> 4) & 15); }

// ---------------- Stockham radix-8 IN-PLACE, N=4096 = 8^4 -------------------
__device__ __forceinline__ void r4core(const float2* a, float2* o, bool inv) {
    float2 s02 = make_float2(a[0].x+a[2].x, a[0].y+a[2].y);
    float2 d02 = make_float2(a[0].x-a[2].x, a[0].y-a[2].y);
    float2 s13 = make_float2(a[1].x+a[3].x, a[1].y+a[3].y);
    float2 d13 = make_float2(a[1].x-a[3].x, a[1].y-a[3].y);
    float2 jd = inv ? make_float2(-d13.y, d13.x) : make_float2(d13.y, -d13.x);
    o[0] = make_float2(s02.x+s13.x, s02.y+s13.y);
    o[1] = make_float2(d02.x+jd.x,  d02.y+jd.y);
    o[2] = make_float2(s02.x-s13.x, s02.y-s13.y);
    o[3] = make_float2(d02.x-jd.x,  d02.y-jd.y);
}

// In-place radix-8 stage: per stage, thread tid reads buf[tid + m*512]
// (disjoint across threads), barrier, then writes its 8 outputs.
// Single 4096-entry buffer; 512-entry twiddle table; blockDim.x == 512.
__device__ __forceinline__ void stockham8_ip(float2* buf, const float2* tw, bool inv) {
    const float S = 0.70710678118654752f;
    #pragma unroll 1
    for (int s = 0; s < 4; s++) {
        int t3 = 3*s;
        int mask = (1<<t3) - 1;
        int idx = threadIdx.x;
        int p = idx >> t3, q = idx & mask;
        int bp = p << t3;
        float2 a[8];
        #pragma unroll
        for (int m = 0; m < 8; m++) a[m] = buf[FSW(idx + m*512)];
        __syncthreads();                       // all reads done before any write
        float2 ev[4] = {a[0],a[2],a[4],a[6]};
        float2 od[4] = {a[1],a[3],a[5],a[7]};
        float2 E[4], O[4];
        r4core(ev, E, inv);
        r4core(od, O, inv);
        float2 w81 = inv ? make_float2(S,  S) : make_float2(S, -S);
        float2 w83 = inv ? make_float2(-S, S) : make_float2(-S,-S);
        O[1] = cmulf(O[1], w81);
        O[2] = inv ? make_float2(-O[2].y, O[2].x) : make_float2(O[2].y, -O[2].x);
        O[3] = cmulf(O[3], w83);
        float2 A[8];
        #pragma unroll
        for (int j = 0; j < 4; j++) {
            A[j]   = make_float2(E[j].x+O[j].x, E[j].y+O[j].y);
            A[j+4] = make_float2(E[j].x-O[j].x, E[j].y-O[j].y);
        }
        int dbase = q + 8*bp;
        float2 w1 = tw[bp];
        if (inv) w1.y = -w1.y;
        float2 w = w1;
        buf[FSW(dbase)] = A[0];
        buf[FSW(dbase + (1<<t3))] = cmulf(A[1], w);
        #pragma unroll
        for (int j = 2; j < 8; j++) {
            w = cmulf(w, w1);
            buf[FSW(dbase + (j<<t3))] = cmulf(A[j], w);
        }
        __syncthreads();                       // writes visible before next stage reads
    }
}

#define TWN 512
#define FFT_SMEM ((4096+TWN) * (int)sizeof(float2))   /* 36864 B -> 4 CTAs/SM (thread cap) */

// ---------------- combined: forward FFT (blocks 0..511) + folds (512..607) --
__global__ void __launch_bounds__(512) k_fwd_prep(const float* __restrict__ u,
                                                  const float* __restrict__ C2,
                                                  const float* __restrict__ Bb2,
                                                  const float* __restrict__ Dm) {
    extern __shared__ float2 sm[];
    if (blockIdx.x < 512) {
        float2* sa = sm; float2* tw = sm+4096;
        int r0 = blockIdx.x*2;
        int b = r0 >> 7, h0 = r0 & 127;
        const float* u0 = u + (size_t)r0*Ld;
        for (int t = threadIdx.x; t < Ld; t += blockDim.x)
            sa[FSW(t)] = make_float2(u0[t], u0[t+Ld]);
        for (int k = threadIdx.x; k < TWN; k += blockDim.x) {
            float s,c; sincospif(-(float)k/2048.0f,&s,&c); tw[k]=make_float2(c,s);
        }
        __syncthreads();
        stockham8_ip(sa, tw, false);
        size_t o1 = (size_t)h0*NCOLP + b*LF;
        size_t o2 = o1 + NCOLP;
        for (int k = threadIdx.x; k < LF; k += blockDim.x) {
            float2 zk = sa[FSW(k)];
            float2 zn = sa[FSW((4096-k)&4095)];
            float2 x1 = make_float2(0.5f*(zk.x+zn.x), 0.5f*(zk.y-zn.y));
            float2 x2 = make_float2(0.5f*(zk.y+zn.y), 0.5f*(zn.x-zk.x));
            __nv_bfloat16 h, l;
            split2(x1.x,h,l); g_Pb[0][o1+k]=h; g_Pb[1][o1+k]=l;
            split2(x1.y,h,l); g_Pb[2][o1+k]=h; g_Pb[3][o1+k]=l;
            split2(x2.x,h,l); g_Pb[0][o2+k]=h; g_Pb[1][o2+k]=l;
            split2(x2.y,h,l); g_Pb[2][o2+k]=h; g_Pb[3][o2+k]=l;
        }
    } else {
        // ----- fold path: 4 rows per block, 512 threads
        float2* twH = sm;            // 128
        float2* vv  = sm + 128;      // 4*128 scratch (D~ blocks)
        int t = threadIdx.x;
        if (t < 128) { float s,c; sincospif(-(float)t/64.0f,&s,&c); twH[t]=make_float2(c,s); }
        __syncthreads();
        int grp = blockIdx.x - 512;     // 0..95
        int sub = t >> 7, inner = t & 127;
        __nv_bfloat16 h, l;
        if (grp < 32) {
            int p = grp*4 + sub, m = inner;
            float2 acc = make_float2(0.f,0.f);
            for (int q = 0; q < 128; q++) {
                float2 w = twH[(q*m)&127];
                float br = Bb2[(p*128+q)*2], bi = Bb2[(p*128+q)*2+1];
                acc.x += br*w.x - bi*w.y;
                acc.y += br*w.y + bi*w.x;
            }
            int idx = p*128 + m;        // [row=p][k=m]
            split2(acc.x,h,l); g_AB[0][idx]=h; g_AB[1][idx]=l;
            split2(acc.y,h,l); g_AB[2][idx]=h; g_AB[3][idx]=l;
        } else if (grp < 64) {
            int n = (grp-32)*4 + sub, p = inner;
            float2 acc = make_float2(0.f,0.f);
            for (int hh = 0; hh < 128; hh++) {
                float2 w = twH[(n*hh)&127]; w.y = -w.y;
                float cr = C2[(hh*128+p)*2], ci = C2[(hh*128+p)*2+1];
                acc.x += cr*w.x - ci*w.y;
                acc.y += cr*w.y + ci*w.x;
            }
            acc.x *= (1.0f/128.0f); acc.y *= (1.0f/128.0f);
            int idx = n*256 + p;        // [row=n][k=p]
            split2(acc.x,h,l); g_AE[0][idx]=h; g_AE[1][idx]=l;
            split2(acc.y,h,l); g_AE[2][idx]=h; g_AE[3][idx]=l;
        } else {
            int n = (grp-64)*4 + sub;
            {   // phase 1: vv[sub][q] = sum_h conj(F[n,h]) * D[h,q]
                int q = inner;
                float2 acc = make_float2(0.f,0.f);
                for (int hh = 0; hh < 128; hh++) {
                    float2 w = twH[(n*hh)&127];
                    float d = Dm[hh*128+q];
                    acc.x += d*w.x;
                    acc.y -= d*w.y;
                }
                vv[sub*128 + q] = acc;
            }
            __syncthreads();
            {   // phase 2: D~[n][m] = (1/H) sum_q vv[sub][q] * F[q,m]
                int m = inner;
                float2 acc = make_float2(0.f,0.f);
                for (int q = 0; q < 128; q++) {
                    float2 w = twH[(q*m)&127];
                    float2 vq = vv[sub*128 + q];
                    acc.x += vq.x*w.x - vq.y*w.y;
                    acc.y += vq.x*w.y + vq.y*w.x;
                }
                acc.x *= (1.0f/128.0f); acc.y *= (1.0f/128.0f);
                int idx = n*256 + 128 + m;   // [row=n][k=128+m]
                split2(acc.x,h,l); g_AE[0][idx]=h; g_AE[1][idx]=l;
                split2(acc.y,h,l); g_AE[2][idx]=h; g_AE[3][idx]=l;
            }
        }
    }
}

// ---------------- fused tensor-core pipeline (FROZEN from round 11) ---------
#define USTR 72
#define UPL  (128*USTR)
#define AKSTR 40
#define APL2 (128*AKSTR)
#define FUSED_SMEM ((8*UPL + 2*4*APL2) * 2)   /* 229376 bytes */

__device__ __forceinline__ uint32_t cvta_s(const void* p) {
    return (uint32_t)__cvta_generic_to_shared(p);
}
__device__ __forceinline__ void cp16(uint32_t s, const void* g) {
    asm volatile("cp.async.cg.shared.global [%0], [%1], 16;" :: "r"(s), "l"(g));
}
__device__ __forceinline__ void cp_commit() { asm volatile("cp.async.commit_group;"); }
__device__ __forceinline__ void cp_wait1()  { asm volatile("cp.async.wait_group 1;"); }
__device__ __forceinline__ void ldsm_x4(uint32_t& r0, uint32_t& r1, uint32_t& r2, uint32_t& r3,
                                        uint32_t addr) {
    asm volatile("ldmatrix.sync.aligned.m8n8.x4.shared.b16 {%0,%1,%2,%3}, [%4];"
                 : "=r"(r0), "=r"(r1), "=r"(r2), "=r"(r3) : "r"(addr));
}
__device__ __forceinline__ void ldsm_x4t(uint32_t& r0, uint32_t& r1, uint32_t& r2, uint32_t& r3,
                                         uint32_t addr) {
    asm volatile("ldmatrix.sync.aligned.m8n8.x4.trans.shared.b16 {%0,%1,%2,%3}, [%4];"
                 : "=r"(r0), "=r"(r1), "=r"(r2), "=r"(r3) : "r"(addr));
}
__device__ __forceinline__ void mma_bf16(float* c, const uint32_t* a, const uint32_t* b) {
    asm volatile("mma.sync.aligned.m16n8k16.row.col.f32.bf16.bf16.f32 "
                 "{%0,%1,%2,%3}, {%4,%5,%6,%7}, {%8,%9}, {%0,%1,%2,%3};"
                 : "+f"(c[0]), "+f"(c[1]), "+f"(c[2]), "+f"(c[3])
                 : "r"(a[0]), "r"(a[1]), "r"(a[2]), "r"(a[3]), "r"(b[0]), "r"(b[1]));
}

__global__ void __launch_bounds__(256, 1) k_fused(const float* __restrict__ Lam) {
    extern __shared__ __nv_bfloat16 smem[];
    __nv_bfloat16* Ub = smem;
    __nv_bfloat16* Wb = smem + 4*UPL;
    __nv_bfloat16* Ab = smem + 8*UPL;

    const int tid  = threadIdx.x;
    const int warp = tid >> 5, lane = tid & 31;
    const int wm = warp & 3, wn = warp >> 2;
    const int col0 = blockIdx.x*NT;
    const int l16 = lane & 15, lhi = (lane >> 4) << 3;

    float accP[2][4][4], accQ[2][4][4], accI[2][4][4];
    #pragma unroll
    for (int mf=0;mf<2;mf++)
        #pragma unroll
        for (int nf=0;nf<4;nf++)
            #pragma unroll
            for (int r=0;r<4;r++) { accP[mf][nf][r]=0.f; accQ[mf][nf][r]=0.f; accI[mf][nf][r]=0.f; }

    auto stageU = [&]() {
        #pragma unroll
        for (int i = 0; i < 16; i++) {
            int idx = tid + i*256;
            int pl = idx >> 10, rem = idx & 1023;
            int row = rem >> 3, c = rem & 7;
            cp16(cvta_s(Ub + pl*UPL + row*USTR + c*8),
                 g_Pb[pl] + (size_t)row*NCOLP + col0 + c*8);
        }
    };
    auto stageA = [&](int cc) {
        const __nv_bfloat16* Asrc;
        int ks, aplg, k0;
        if (cc < 4) { Asrc = g_AB[0]; ks = 128; aplg = 128*128; k0 = cc*32; }
        else        { Asrc = g_AE[0]; ks = 256; aplg = 128*256; k0 = (cc-4)*32; }
        __nv_bfloat16* dst = Ab + (cc&1)*(4*APL2);
        #pragma unroll
        for (int i = 0; i < 8; i++) {
            int idx = tid + i*256;
            int pl = idx >> 9, rem = idx & 511;
            int row = rem >> 2, c = rem & 3;
            cp16(cvta_s(dst + pl*APL2 + row*AKSTR + c*8),
                 Asrc + (size_t)pl*aplg + (size_t)row*ks + k0 + c*8);
        }
    };

    stageU(); stageA(0); cp_commit();

    #pragma unroll 1
    for (int c = 0; c < 12; c++) {
        if (c+1 < 12) stageA(c+1);
        cp_commit();

        if (c == 4) {
            #pragma unroll
            for (int mf = 0; mf < 2; mf++) {
                #pragma unroll
                for (int h = 0; h < 2; h++) {
                    int row = wm*32 + mf*16 + (lane>>2) + h*8;
                    float lre = Lam[2*row], lim = Lam[2*row+1];
                    #pragma unroll
                    for (int nf = 0; nf < 4; nf++) {
                        int col = wn*32 + nf*8 + (lane&3)*2;
                        float vr0 = accP[mf][nf][h*2+0] - accQ[mf][nf][h*2+0];
                        float vi0 = accI[mf][nf][h*2+0];
                        float vr1 = accP[mf][nf][h*2+1] - accQ[mf][nf][h*2+1];
                        float vi1 = accI[mf][nf][h*2+1];
                        int gc = col0 + col;
                        int l0 = gc % 2049, l1 = (gc+1) % 2049;
                        float om0 = 1.5339807878856412e-3f * (float)l0;
                        float om1 = 1.5339807878856412e-3f * (float)l1;
                        float dre = -lre;
                        float di0 = om0 - lim, di1 = om1 - lim;
                        float iv0 = 1.0f/(dre*dre + di0*di0);
                        float iv1 = 1.0f/(dre*dre + di1*di1);
                        float kr0 = dre*iv0, ki0 = -di0*iv0;
                        float kr1 = dre*iv1, ki1 = -di1*iv1;
                        float tr0 = vr0*kr0 - vi0*ki0, ti0 = vr0*ki0 + vi0*kr0;
                        float tr1 = vr1*kr1 - vi1*ki1, ti1 = vr1*ki1 + vi1*kr1;
                        int off = row*USTR + col;
                        __nv_bfloat16 h0,l0b,h1,l1b;
                        split2(tr0,h0,l0b); split2(tr1,h1,l1b);
                        *reinterpret_cast<__nv_bfloat162*>(&Wb[0*UPL+off]) = __nv_bfloat162(h0,h1);
                        *reinterpret_cast<__nv_bfloat162*>(&Wb[1*UPL+off]) = __nv_bfloat162(l0b,l1b);
                        split2(ti0,h0,l0b); split2(ti1,h1,l1b);
                        *reinterpret_cast<__nv_bfloat162*>(&Wb[2*UPL+off]) = __nv_bfloat162(h0,h1);
                        *reinterpret_cast<__nv_bfloat162*>(&Wb[3*UPL+off]) = __nv_bfloat162(l0b,l1b);
                        #pragma unroll
                        for (int r=0;r<2;r++) {
                            accP[mf][nf][h*2+r]=0.f; accQ[mf][nf][h*2+r]=0.f; accI[mf][nf][h*2+r]=0.f;
                        }
                    }
                }
            }
        }
        cp_wait1();
        __syncthreads();

        const __nv_bfloat16* Bbase; int krow;
        if (c < 4)       { Bbase = Ub; krow = c*32; }
        else if (c < 8)  { Bbase = Wb; krow = (c-4)*32; }
        else             { Bbase = Ub; krow = (c-8)*32; }
        const __nv_bfloat16* As = Ab + (c&1)*(4*APL2);

        uint32_t b[2][4][4][2];
        #pragma unroll
        for (int half = 0; half < 2; half++)
            #pragma unroll
            for (int q = 0; q < 4; q++)
                #pragma unroll
                for (int np = 0; np < 2; np++) {
                    uint32_t addr = cvta_s(Bbase + q*UPL + (krow + half*16 + l16)*USTR
                                           + wn*32 + np*16 + lhi);
                    ldsm_x4t(b[half][q][2*np][0], b[half][q][2*np][1],
                             b[half][q][2*np+1][0], b[half][q][2*np+1][1], addr);
                }
        #pragma unroll
        for (int half = 0; half < 2; half++) {
            const int kk = half*16;
            #pragma unroll
            for (int p = 0; p < 4; p++) {
                uint32_t a[2][4];
                #pragma unroll
                for (int mf = 0; mf < 2; mf++) {
                    uint32_t addr = cvta_s(As + p*APL2 + (wm*32 + mf*16 + l16)*AKSTR + kk + lhi);
                    ldsm_x4(a[mf][0], a[mf][1], a[mf][2], a[mf][3], addr);
                }
                #pragma unroll
                for (int mf = 0; mf < 2; mf++)
                    #pragma unroll
                    for (int nf = 0; nf < 4; nf++) {
                        if (p == 0) {
                            mma_bf16(accP[mf][nf], a[mf], b[half][0][nf]);
                            mma_bf16(accP[mf][nf], a[mf], b[half][1][nf]);
                            mma_bf16(accI[mf][nf], a[mf], b[half][2][nf]);
                            mma_bf16(accI[mf][nf], a[mf], b[half][3][nf]);
                        } else if (p == 1) {
                            mma_bf16(accP[mf][nf], a[mf], b[half][0][nf]);
                            mma_bf16(accI[mf][nf], a[mf], b[half][2][nf]);
                        } else if (p == 2) {
                            mma_bf16(accQ[mf][nf], a[mf], b[half][2][nf]);
                            mma_bf16(accQ[mf][nf], a[mf], b[half][3][nf]);
                            mma_bf16(accI[mf][nf], a[mf], b[half][0][nf]);
                            mma_bf16(accI[mf][nf], a[mf], b[half][1][nf]);
                        } else {
                            mma_bf16(accQ[mf][nf], a[mf], b[half][2][nf]);
                            mma_bf16(accI[mf][nf], a[mf], b[half][0][nf]);
                        }
                    }
            }
        }
        __syncthreads();
    }

    #pragma unroll
    for (int mf = 0; mf < 2; mf++) {
        #pragma unroll
        for (int h = 0; h < 2; h++) {
            int row = wm*32 + mf*16 + (lane>>2) + h*8;
            #pragma unroll
            for (int nf = 0; nf < 4; nf++) {
                int col = col0 + wn*32 + nf*8 + (lane&3)*2;
                float4 o = make_float4(accP[mf][nf][h*2+0] - accQ[mf][nf][h*2+0],
                                       accI[mf][nf][h*2+0],
                                       accP[mf][nf][h*2+1] - accQ[mf][nf][h*2+1],
                                       accI[mf][nf][h*2+1]);
                *reinterpret_cast<float4*>(&g_Ys[(size_t)row*NCOLP + col]) = o;
            }
        }
    }
}

// ---------------- inverse FFT + GELU ----------------------------------------
__global__ void __launch_bounds__(512) k_fft_inv(float* __restrict__ out) {
    extern __shared__ float2 sm[];
    float2* sa = sm; float2* tw = sm+4096;
    int r0 = blockIdx.x*2;
    int b = r0 >> 7, h0 = r0 & 127;
    const float2* in0 = g_Ys + (size_t)h0*NCOLP + b*LF;
    for (int k = threadIdx.x; k < LF; k += blockDim.x) {
        float2 y1 = in0[k];
        float2 y2 = in0[NCOLP+k];
        if (k == 0 || k == 2048) { y1.y = 0.f; y2.y = 0.f; }
        sa[FSW(k)] = make_float2(y1.x - y2.y, y1.y + y2.x);
        if (k > 0 && k < 2048)
            sa[FSW(4096-k)] = make_float2(y1.x + y2.y, y2.x - y1.y);
    }
    for (int k = threadIdx.x; k < TWN; k += blockDim.x) {
        float s,c; sincospif(-(float)k/2048.0f,&s,&c); tw[k]=make_float2(c,s);
    }
    __syncthreads();
    stockham8_ip(sa, tw, true);
    float* o0 = out + (size_t)r0*Ld;
    const float sc = 1.0f/4096.0f;
    for (int t = threadIdx.x; t < Ld; t += blockDim.x) {
        float2 v = sa[FSW(t)];
        float v0 = v.x*sc, v1 = v.y*sc;
        o0[t]    = 0.5f*v0*(1.0f + erff(v0*0.70710678118654752f));
        o0[t+Ld] = 0.5f*v1*(1.0f + erff(v1*0.70710678118654752f));
    }
}

// ---------------- launch ----------------------------------------------------
extern "C" void kernel_launch(void* const* d_in, const int* in_sizes, int n_in,
                              void* d_out, int out_size) {
    (void)in_sizes; (void)n_in; (void)out_size;
    const float* u   = (const float*)d_in[0];
    const float* C2  = (const float*)d_in[1];
    const float* Bb2 = (const float*)d_in[2];
    const float* Dm  = (const float*)d_in[3];
    const float* Lam = (const float*)d_in[4];
    float* out = (float*)d_out;

    cudaFuncSetAttribute(k_fwd_prep, cudaFuncAttributeMaxDynamicSharedMemorySize, FFT_SMEM);
    cudaFuncSetAttribute(k_fft_inv,  cudaFuncAttributeMaxDynamicSharedMemorySize, FFT_SMEM);
    cudaFuncSetAttribute(k_fused,    cudaFuncAttributeMaxDynamicSharedMemorySize, FUSED_SMEM);

    k_fwd_prep<<<608, 512, FFT_SMEM>>>(u, C2, Bb2, Dm);
    k_fused<<<NCOLP/NT, 256, FUSED_SMEM>>>(Lam);
    k_fft_inv<<<512, 512, FFT_SMEM>>>(out);
}